// round 2
// baseline (speedup 1.0000x reference)
#include <cuda_runtime.h>
#include <cuda_bf16.h>

// Problem constants (fixed by setup_inputs)
#define S_LEN 2048
#define BATCH 2
#define HID   2048
#define NHEAD 16
#define DHEAD 128
#define QKV_N (3 * HID)          // 6144
#define ROWS  (S_LEN * BATCH)    // 4096
#define MIXED_ROWSTRIDE (QKV_N)  // per (s,b) row of mixed

// Scratch buffers (no allocations allowed)
__device__ float g_mixed[(size_t)ROWS * QKV_N];   // [s*B+b][6144]
__device__ float g_ctx[(size_t)ROWS * HID];       // [s*B+b][2048]

// ---------------------------------------------------------------------------
// Generic tiled SGEMM: C[M,N] = A[M,K] @ B[K,N] (+ bias[N] if bias != null)
// BM=BN=128, BK=8, 256 threads, 8x8 per-thread microtile.
// M,N divisible by 128; K divisible by 8 (true for all calls here).
// ---------------------------------------------------------------------------
__global__ void __launch_bounds__(256, 2)
sgemm_bias_kernel(int M, int N, int K,
                  const float* __restrict__ A,
                  const float* __restrict__ B,
                  const float* __restrict__ bias,
                  float* __restrict__ C)
{
    __shared__ float As[8][128];
    __shared__ float Bs[8][128];

    const int tid = threadIdx.x;
    const int tx = tid & 15;       // 0..15 -> col groups of 8
    const int ty = tid >> 4;       // 0..15 -> row groups of 8
    const int rowBase = blockIdx.y * 128;
    const int colBase = blockIdx.x * 128;

    const int aRow = tid >> 1;            // 0..127
    const int aCol = (tid & 1) * 4;       // 0 or 4
    const int bRow = tid >> 5;            // 0..7
    const int bCol = (tid & 31) * 4;      // 0..124

    const float* Aptr = A + (size_t)(rowBase + aRow) * K + aCol;
    const float* Bptr = B + (size_t)bRow * N + colBase + bCol;

    float acc[8][8];
#pragma unroll
    for (int i = 0; i < 8; i++)
#pragma unroll
        for (int j = 0; j < 8; j++) acc[i][j] = 0.0f;

    for (int k0 = 0; k0 < K; k0 += 8) {
        float4 av = *(const float4*)(Aptr + k0);
        float4 bv = *(const float4*)(Bptr + (size_t)k0 * N);
        As[aCol + 0][aRow] = av.x;
        As[aCol + 1][aRow] = av.y;
        As[aCol + 2][aRow] = av.z;
        As[aCol + 3][aRow] = av.w;
        *(float4*)&Bs[bRow][bCol] = bv;
        __syncthreads();

#pragma unroll
        for (int kk = 0; kk < 8; kk++) {
            float a[8], b[8];
            *(float4*)(a)     = *(const float4*)&As[kk][ty * 8];
            *(float4*)(a + 4) = *(const float4*)&As[kk][ty * 8 + 4];
            *(float4*)(b)     = *(const float4*)&Bs[kk][tx * 8];
            *(float4*)(b + 4) = *(const float4*)&Bs[kk][tx * 8 + 4];
#pragma unroll
            for (int i = 0; i < 8; i++)
#pragma unroll
                for (int j = 0; j < 8; j++)
                    acc[i][j] = fmaf(a[i], b[j], acc[i][j]);
        }
        __syncthreads();
    }

#pragma unroll
    for (int i = 0; i < 8; i++) {
        const int r = rowBase + ty * 8 + i;
#pragma unroll
        for (int j = 0; j < 8; j += 4) {
            const int c = colBase + tx * 8 + j;
            float4 v;
            float b0 = 0.f, b1 = 0.f, b2 = 0.f, b3 = 0.f;
            if (bias) {
                b0 = bias[c]; b1 = bias[c + 1]; b2 = bias[c + 2]; b3 = bias[c + 3];
            }
            v.x = acc[i][j + 0] + b0;
            v.y = acc[i][j + 1] + b1;
            v.z = acc[i][j + 2] + b2;
            v.w = acc[i][j + 3] + b3;
            *(float4*)&C[(size_t)r * N + c] = v;
        }
    }
}

// ---------------------------------------------------------------------------
// Flash attention (fp32, causal + bool mask), one block per (q-tile, head, b)
// Br = Bc = 64, D = 128. Online softmax. smem ~122.8 KB (dynamic).
// Transposed padded tiles (stride 68) => float4 conflict-free GEMM reads.
// ---------------------------------------------------------------------------
#define BR 64
#define BC 64
#define PSTR 68   // padded stride for transposed [D or Bc][64] tiles

#define SM_QT   0
#define SM_KT   (DHEAD * PSTR)                 // 8704
#define SM_V    (SM_KT + DHEAD * PSTR)        // 17408
#define SM_PT   (SM_V + BC * DHEAD)           // 25600
#define SM_M    (SM_PT + BC * PSTR)           // 29952
#define SM_L    (SM_M + BR)
#define SM_AL   (SM_L + BR)
#define SM_RED  (SM_AL + BR)                  // 256 floats
#define SM_MASK (SM_RED + 256)                // 4096 bytes as uchar
#define ATTN_SMEM_BYTES ((SM_MASK) * 4 + BR * BC)

__global__ void __launch_bounds__(256, 1)
attn_kernel(const float* __restrict__ mixed,
            const unsigned char* __restrict__ mask,
            float* __restrict__ ctx)
{
    extern __shared__ float sm[];
    float* sQt = sm + SM_QT;          // [128][68] (Qt[c][r])
    float* sKt = sm + SM_KT;          // [128][68]
    float* sV  = sm + SM_V;           // [64][128]
    float* sPt = sm + SM_PT;          // [64][68] (Pt[c][r])
    float* sM  = sm + SM_M;           // [64]
    float* sL  = sm + SM_L;           // [64]
    float* sAl = sm + SM_AL;          // [64]
    float* sRed = sm + SM_RED;        // [256]
    unsigned char* sMask = (unsigned char*)(sm + SM_MASK); // [64][64]

    const int tid = threadIdx.x;
    const int q0 = blockIdx.x * BR;
    const int h  = blockIdx.y;
    const int b  = blockIdx.z;

    const size_t rowStride = (size_t)BATCH * QKV_N;   // stride between s
    const float* Qbase = mixed + (size_t)b * QKV_N + h * (3 * DHEAD);
    const float* Kbase = Qbase + DHEAD;
    const float* Vbase = Qbase + 2 * DHEAD;

    const int ty = tid >> 4;   // 0..15
    const int tx = tid & 15;   // 0..15

    // Load Q tile transposed: 64x128 -> Qt[c][r]
    for (int base = tid * 4; base < BR * DHEAD; base += 256 * 4) {
        int r = base / DHEAD, c = base % DHEAD;
        float4 v = *(const float4*)(Qbase + (size_t)(q0 + r) * rowStride + c);
        sQt[(c + 0) * PSTR + r] = v.x;
        sQt[(c + 1) * PSTR + r] = v.y;
        sQt[(c + 2) * PSTR + r] = v.z;
        sQt[(c + 3) * PSTR + r] = v.w;
    }
    if (tid < BR) { sM[tid] = -1e30f; sL[tid] = 0.0f; }

    float accO[4][8];
#pragma unroll
    for (int i = 0; i < 4; i++)
#pragma unroll
        for (int j = 0; j < 8; j++) accO[i][j] = 0.0f;

    __syncthreads();

    const int ntiles = blockIdx.x + 1;   // causal: only k0 <= q0 tiles
    for (int t = 0; t < ntiles; t++) {
        const int k0 = t * BC;

        // Load K (transposed) and V tiles
        for (int base = tid * 4; base < BC * DHEAD; base += 256 * 4) {
            int r = base / DHEAD, c = base % DHEAD;
            float4 kv = *(const float4*)(Kbase + (size_t)(k0 + r) * rowStride + c);
            sKt[(c + 0) * PSTR + r] = kv.x;
            sKt[(c + 1) * PSTR + r] = kv.y;
            sKt[(c + 2) * PSTR + r] = kv.z;
            sKt[(c + 3) * PSTR + r] = kv.w;
            float4 vv = *(const float4*)(Vbase + (size_t)(k0 + r) * rowStride + c);
            *(float4*)&sV[r * DHEAD + c] = vv;
        }
        // Stage mask bytes: mask[b][0][q0+r][k0+c]
        {
            const unsigned char* mb = mask + (size_t)b * S_LEN * S_LEN;
            int mr = tid >> 2, mc = (tid & 3) * 16;
            uint4 mv = *(const uint4*)(mb + (size_t)(q0 + mr) * S_LEN + k0 + mc);
            *(uint4*)&sMask[mr * BC + mc] = mv;
        }
        __syncthreads();

        // Phase A: S = Q K^T * scale, masked; store transposed Pt[c][r]
        {
            float s[4][4];
#pragma unroll
            for (int i = 0; i < 4; i++)
#pragma unroll
                for (int j = 0; j < 4; j++) s[i][j] = 0.0f;

#pragma unroll 4
            for (int kk = 0; kk < DHEAD; kk++) {
                float a[4], bb[4];
                *(float4*)a  = *(const float4*)&sQt[kk * PSTR + ty * 4];
                *(float4*)bb = *(const float4*)&sKt[kk * PSTR + tx * 4];
#pragma unroll
                for (int i = 0; i < 4; i++)
#pragma unroll
                    for (int j = 0; j < 4; j++)
                        s[i][j] = fmaf(a[i], bb[j], s[i][j]);
            }
            const float scale = 0.0883883476483184405f;  // 1/sqrt(128)
#pragma unroll
            for (int i = 0; i < 4; i++) {
                const int r = ty * 4 + i;
                const int qi = q0 + r;
#pragma unroll
                for (int j = 0; j < 4; j++) {
                    const int c = tx * 4 + j;
                    const int kj = k0 + c;
                    float val = s[i][j] * scale;
                    if (kj > qi || sMask[r * BC + c]) val = -10000.0f;
                    sPt[c * PSTR + r] = val;
                }
            }
        }
        __syncthreads();

        // Phase B1: partial row max (thread: row = tid&63, 16 cols)
        {
            const int r = tid & 63, ch = tid >> 6, cb = ch * 16;
            float mloc = -1e30f;
#pragma unroll
            for (int c = 0; c < 16; c++)
                mloc = fmaxf(mloc, sPt[(cb + c) * PSTR + r]);
            sRed[ch * 64 + r] = mloc;
        }
        __syncthreads();
        if (tid < BR) {
            float mnew = fmaxf(fmaxf(sRed[tid], sRed[64 + tid]),
                               fmaxf(sRed[128 + tid], sRed[192 + tid]));
            float mold = sM[tid];
            mnew = fmaxf(mold, mnew);
            float alpha = __expf(mold - mnew);
            sAl[tid] = alpha;
            sM[tid] = mnew;
            sL[tid] *= alpha;
        }
        __syncthreads();

        // Phase B2: exponentiate in place + partial sums
        {
            const int r = tid & 63, ch = tid >> 6, cb = ch * 16;
            const float mnew = sM[r];
            float ssum = 0.0f;
#pragma unroll
            for (int c = 0; c < 16; c++) {
                float p = __expf(sPt[(cb + c) * PSTR + r] - mnew);
                sPt[(cb + c) * PSTR + r] = p;
                ssum += p;
            }
            sRed[ch * 64 + r] = ssum;
        }
        __syncthreads();
        if (tid < BR)
            sL[tid] += sRed[tid] + sRed[64 + tid] + sRed[128 + tid] + sRed[192 + tid];

        // Phase C: O = O*alpha + P @ V  (alpha already visible; sPt updated)
        {
            float al[4];
#pragma unroll
            for (int i = 0; i < 4; i++) al[i] = sAl[ty * 4 + i];
#pragma unroll
            for (int i = 0; i < 4; i++)
#pragma unroll
                for (int j = 0; j < 8; j++) accO[i][j] *= al[i];

#pragma unroll 4
            for (int kk = 0; kk < BC; kk++) {
                float a[4], bv[8];
                *(float4*)a        = *(const float4*)&sPt[kk * PSTR + ty * 4];
                *(float4*)(bv)     = *(const float4*)&sV[kk * DHEAD + tx * 8];
                *(float4*)(bv + 4) = *(const float4*)&sV[kk * DHEAD + tx * 8 + 4];
#pragma unroll
                for (int i = 0; i < 4; i++)
#pragma unroll
                    for (int j = 0; j < 8; j++)
                        accO[i][j] = fmaf(a[i], bv[j], accO[i][j]);
            }
        }
        __syncthreads();
    }

    // Epilogue: O /= l, scatter to ctx[(s*B+b)][h*128 + col]
#pragma unroll
    for (int i = 0; i < 4; i++) {
        const int r = ty * 4 + i;
        const float inv = 1.0f / sL[r];
        float* dst = ctx + ((size_t)(q0 + r) * BATCH + b) * HID + h * DHEAD + tx * 8;
        float4 v0, v1;
        v0.x = accO[i][0] * inv; v0.y = accO[i][1] * inv;
        v0.z = accO[i][2] * inv; v0.w = accO[i][3] * inv;
        v1.x = accO[i][4] * inv; v1.y = accO[i][5] * inv;
        v1.z = accO[i][6] * inv; v1.w = accO[i][7] * inv;
        *(float4*)(dst)     = v0;
        *(float4*)(dst + 4) = v1;
    }
}

// Copy proj_bias into the tail of d_out (reference returns (out, proj_bias))
__global__ void bias_tail_kernel(const float* __restrict__ proj_bias,
                                 float* __restrict__ out_tail)
{
    int i = blockIdx.x * blockDim.x + threadIdx.x;
    if (i < HID) out_tail[i] = proj_bias[i];
}

// ---------------------------------------------------------------------------
extern "C" void kernel_launch(void* const* d_in, const int* in_sizes, int n_in,
                              void* d_out, int out_size)
{
    const float* hidden      = (const float*)d_in[0];
    const unsigned char* msk = (const unsigned char*)d_in[1];
    const float* qkv_w       = (const float*)d_in[2];
    const float* qkv_b       = (const float*)d_in[3];
    const float* proj_w      = (const float*)d_in[4];
    const float* proj_b      = (const float*)d_in[5];
    float* out               = (float*)d_out;

    float* mixed;
    float* ctx;
    cudaGetSymbolAddress((void**)&mixed, g_mixed);
    cudaGetSymbolAddress((void**)&ctx, g_ctx);

    cudaFuncSetAttribute(attn_kernel,
                         cudaFuncAttributeMaxDynamicSharedMemorySize,
                         ATTN_SMEM_BYTES);

    // 1) QKV GEMM: mixed[4096,6144] = hidden[4096,2048] @ qkv_w[2048,6144] + b
    {
        dim3 grid(QKV_N / 128, ROWS / 128);
        sgemm_bias_kernel<<<grid, 256>>>(ROWS, QKV_N, HID,
                                         hidden, qkv_w, qkv_b, mixed);
    }
    // 2) Flash attention -> ctx[4096,2048]
    {
        dim3 grid(S_LEN / BR, NHEAD, BATCH);
        attn_kernel<<<grid, 256, ATTN_SMEM_BYTES>>>(mixed, msk, ctx);
    }
    // 3) Projection: out[4096,2048] = ctx @ proj_w (no bias added)
    {
        dim3 grid(HID / 128, ROWS / 128);
        sgemm_bias_kernel<<<grid, 256>>>(ROWS, HID, HID,
                                         ctx, proj_w, (const float*)nullptr, out);
    }
    // 4) Tail: proj_bias copied after the main output
    bias_tail_kernel<<<(HID + 255) / 256, 256>>>(proj_b, out + (size_t)ROWS * HID);
}

// round 5
// speedup vs baseline: 1.7960x; 1.7960x over previous
#include <cuda_runtime.h>
#include <cuda_bf16.h>
#include <cstdint>

// Problem constants (fixed by setup_inputs)
#define S_LEN 2048
#define BATCH 2
#define HID   2048
#define NHEAD 16
#define DHEAD 128
#define QKV_N (3 * HID)          // 6144
#define ROWS  (S_LEN * BATCH)    // 4096

// ---------------------------------------------------------------------------
// Scratch (no allocations allowed anywhere)
// ---------------------------------------------------------------------------
__device__ float g_mixed[(size_t)ROWS * QKV_N];           // [s*B+b][6144]
__device__ float g_ctx[(size_t)ROWS * HID];               // [s*B+b][2048]
__device__ __nv_bfloat16 g_Ahi[(size_t)ROWS * HID];       // activation split (reused)
__device__ __nv_bfloat16 g_Alo[(size_t)ROWS * HID];
__device__ __nv_bfloat16 g_WqT_hi[(size_t)QKV_N * HID];   // qkv_w^T [6144,2048]
__device__ __nv_bfloat16 g_WqT_lo[(size_t)QKV_N * HID];
__device__ __nv_bfloat16 g_WpT_hi[(size_t)HID * HID];     // proj_w^T [2048,2048]
__device__ __nv_bfloat16 g_WpT_lo[(size_t)HID * HID];

// ---------------------------------------------------------------------------
// PTX helpers (sm_80-era features only — must assemble for plain sm_103)
// ---------------------------------------------------------------------------
__device__ __forceinline__ uint32_t smem_u32(const void* p) {
    uint32_t a;
    asm("{ .reg .u64 t; cvta.to.shared.u64 t, %1; cvt.u32.u64 %0, t; }"
        : "=r"(a) : "l"(p));
    return a;
}

#define CP_ASYNC16(dst, src) \
    asm volatile("cp.async.cg.shared.global [%0], [%1], 16;" \
        :: "r"(dst), "l"(src))
#define CP_COMMIT() asm volatile("cp.async.commit_group;" ::: "memory")
#define CP_WAIT1()  asm volatile("cp.async.wait_group 1;" ::: "memory")
#define CP_WAIT0()  asm volatile("cp.async.wait_group 0;" ::: "memory")

__device__ __forceinline__ void ldsm4(uint32_t* r, uint32_t addr) {
    asm volatile("ldmatrix.sync.aligned.m8n8.x4.shared.b16 {%0,%1,%2,%3}, [%4];"
        : "=r"(r[0]), "=r"(r[1]), "=r"(r[2]), "=r"(r[3]) : "r"(addr));
}

__device__ __forceinline__ void mma_bf16(float* c, const uint32_t* a, const uint32_t* b) {
    asm volatile(
        "mma.sync.aligned.m16n8k16.row.col.f32.bf16.bf16.f32 "
        "{%0,%1,%2,%3}, {%4,%5,%6,%7}, {%8,%9}, {%0,%1,%2,%3};"
        : "+f"(c[0]), "+f"(c[1]), "+f"(c[2]), "+f"(c[3])
        : "r"(a[0]), "r"(a[1]), "r"(a[2]), "r"(a[3]), "r"(b[0]), "r"(b[1]));
}

#define SMEM_SWIZZLE_128B(o) ((o) ^ (((o) >> 3) & 0x70))

// ---------------------------------------------------------------------------
// Conversion kernels
// ---------------------------------------------------------------------------
__global__ void split_kernel(const float* __restrict__ X,
                             __nv_bfloat16* __restrict__ hi,
                             __nv_bfloat16* __restrict__ lo, int n4)
{
    int i = blockIdx.x * blockDim.x + threadIdx.x;
    if (i >= n4) return;
    float4 v = ((const float4*)X)[i];
    __nv_bfloat16 h0 = __float2bfloat16(v.x), h1 = __float2bfloat16(v.y);
    __nv_bfloat16 h2 = __float2bfloat16(v.z), h3 = __float2bfloat16(v.w);
    __nv_bfloat16 l0 = __float2bfloat16(v.x - __bfloat162float(h0));
    __nv_bfloat16 l1 = __float2bfloat16(v.y - __bfloat162float(h1));
    __nv_bfloat16 l2 = __float2bfloat16(v.z - __bfloat162float(h2));
    __nv_bfloat16 l3 = __float2bfloat16(v.w - __bfloat162float(h3));
    ((__nv_bfloat162*)hi)[i * 2]     = __halves2bfloat162(h0, h1);
    ((__nv_bfloat162*)hi)[i * 2 + 1] = __halves2bfloat162(h2, h3);
    ((__nv_bfloat162*)lo)[i * 2]     = __halves2bfloat162(l0, l1);
    ((__nv_bfloat162*)lo)[i * 2 + 1] = __halves2bfloat162(l2, l3);
}

// W [K,N] fp32 -> hi/lo [N,K] bf16 (transpose + split)
__global__ void transpose_split_kernel(const float* __restrict__ W,
                                       __nv_bfloat16* __restrict__ hi,
                                       __nv_bfloat16* __restrict__ lo,
                                       int K, int N)
{
    __shared__ float t[32][33];
    int n0 = blockIdx.x * 32, k0 = blockIdx.y * 32;
    int tx = threadIdx.x, ty = threadIdx.y;  // 32 x 8
#pragma unroll
    for (int i = 0; i < 32; i += 8)
        t[ty + i][tx] = W[(size_t)(k0 + ty + i) * N + n0 + tx];
    __syncthreads();
#pragma unroll
    for (int i = 0; i < 32; i += 8) {
        int n = n0 + ty + i;
        int k = k0 + tx;
        float v = t[tx][ty + i];   // = W[k][n]
        __nv_bfloat16 h = __float2bfloat16(v);
        hi[(size_t)n * K + k] = h;
        lo[(size_t)n * K + k] = __float2bfloat16(v - __bfloat162float(h));
    }
}

// ---------------------------------------------------------------------------
// HMMA split-bf16 GEMM: C[M,N] = A[M,K] @ Bt[N,K]^T (+bias)
// BM=BN=128, BK=64, 256 threads (8 warps, 4x2), 3-stage cp.async pipeline.
// Effective fp32 accuracy via (Ahi*Bhi + Ahi*Blo + Alo*Bhi).
// ---------------------------------------------------------------------------
#define G_STAGE 65536                 // Ahi|Alo|Bhi|Blo, 16KB each
#define G_SMEM_BYTES (3 * G_STAGE + 1024)

__global__ void __launch_bounds__(256, 1)
gemm_mma_kernel(int M, int N, int K,
                const __nv_bfloat16* __restrict__ Ahi,
                const __nv_bfloat16* __restrict__ Alo,
                const __nv_bfloat16* __restrict__ Bhi,
                const __nv_bfloat16* __restrict__ Blo,
                const float* __restrict__ bias,
                float* __restrict__ C)
{
    extern __shared__ char smraw[];
    uint32_t sraw = smem_u32(smraw);
    const uint32_t sb = (sraw + 1023u) & ~1023u;   // 1KB-aligned smem base

    const int tid  = threadIdx.x;
    const int lane = tid & 31;
    const int warp = tid >> 5;
    const int wm = warp & 3;          // 0..3 (M)
    const int wn = warp >> 2;         // 0..1 (N)
    const int rowBase = blockIdx.y * 128;
    const int colBase = blockIdx.x * 128;

    const int nch = K >> 6;           // K/64 chunks

    // ---- stage loader (cp.async, swizzled) ----
    auto load_stage = [&](int stage, int k0) {
        const uint32_t sBase = sb + stage * G_STAGE;
#pragma unroll
        for (int tIdx = 0; tIdx < 4; tIdx++) {
            const __nv_bfloat16* src =
                (tIdx == 0) ? Ahi : (tIdx == 1) ? Alo : (tIdx == 2) ? Bhi : Blo;
            const int rb = (tIdx < 2) ? rowBase : colBase;
#pragma unroll
            for (int i = 0; i < 4; i++) {
                int s = tid + i * 256;
                int r = s >> 3, c16 = s & 7;
                const void* g = src + (size_t)(rb + r) * K + k0 + c16 * 8;
                uint32_t d = sBase + tIdx * 16384 + SMEM_SWIZZLE_128B(r * 128 + c16 * 16);
                CP_ASYNC16(d, g);
            }
        }
    };

    float c[2][8][4];
#pragma unroll
    for (int mt = 0; mt < 2; mt++)
#pragma unroll
        for (int nt = 0; nt < 8; nt++)
#pragma unroll
            for (int j = 0; j < 4; j++) c[mt][nt][j] = 0.0f;

    // Prologue: stages 0 and 1 in flight
    load_stage(0, 0);
    CP_COMMIT();
    load_stage(1, 64);
    CP_COMMIT();

    // ldmatrix lane addressing (tile-relative, constant across chunks)
    const int aRow  = wm * 32 + (lane & 15);
    const int aKoff = (lane >> 4) << 4;                       // +16B for lanes>=16
    const int bRow  = wn * 64 + (lane & 7) + ((lane >> 4) << 3); // +8 rows for lanes>=16
    const int bKoff = ((lane >> 3) & 1) << 4;                 // +16B for odd 8-lane group

    for (int ch = 0; ch < nch; ch++) {
        CP_WAIT1();
        __syncthreads();
        if (ch + 2 < nch) {
            load_stage((ch + 2) % 3, (ch + 2) << 6);
            CP_COMMIT();
        } else {
            CP_COMMIT();   // keep group counts consistent for WAIT1
        }

        const uint32_t sA_hi = sb + (ch % 3) * G_STAGE;
        const uint32_t sA_lo = sA_hi + 16384;
        const uint32_t sB_hi = sA_hi + 32768;
        const uint32_t sB_lo = sA_hi + 49152;

#pragma unroll
        for (int ks = 0; ks < 4; ks++) {
            uint32_t aH[2][4], aL[2][4];
            const int kbA = ks * 32 + aKoff;
#pragma unroll
            for (int mt = 0; mt < 2; mt++) {
                uint32_t off = SMEM_SWIZZLE_128B((aRow + mt * 16) * 128 + kbA);
                ldsm4(aH[mt], sA_hi + off);
                ldsm4(aL[mt], sA_lo + off);
            }
            uint32_t bH[4][4], bL[4][4];
            const int kbB = ks * 32 + bKoff;
#pragma unroll
            for (int nt = 0; nt < 4; nt++) {
                uint32_t off = SMEM_SWIZZLE_128B((bRow + nt * 16) * 128 + kbB);
                ldsm4(bH[nt], sB_hi + off);
                ldsm4(bL[nt], sB_lo + off);
            }
#pragma unroll
            for (int mt = 0; mt < 2; mt++)
#pragma unroll
                for (int nt = 0; nt < 4; nt++) {
                    mma_bf16(c[mt][nt * 2],     aH[mt], &bH[nt][0]);
                    mma_bf16(c[mt][nt * 2],     aH[mt], &bL[nt][0]);
                    mma_bf16(c[mt][nt * 2],     aL[mt], &bH[nt][0]);
                    mma_bf16(c[mt][nt * 2 + 1], aH[mt], &bH[nt][2]);
                    mma_bf16(c[mt][nt * 2 + 1], aH[mt], &bL[nt][2]);
                    mma_bf16(c[mt][nt * 2 + 1], aL[mt], &bH[nt][2]);
                }
        }
        __syncthreads();
    }

    // Epilogue: c[mt][nt] quad layout -> global fp32 (+bias)
    const int qr = lane >> 2;
    const int qc = (lane & 3) * 2;
#pragma unroll
    for (int mt = 0; mt < 2; mt++) {
        const int row = rowBase + wm * 32 + mt * 16 + qr;
#pragma unroll
        for (int nt = 0; nt < 8; nt++) {
            const int col = colBase + wn * 64 + nt * 8 + qc;
            float b0 = 0.0f, b1 = 0.0f;
            if (bias) { b0 = bias[col]; b1 = bias[col + 1]; }
            float2 v0 = make_float2(c[mt][nt][0] + b0, c[mt][nt][1] + b1);
            float2 v1 = make_float2(c[mt][nt][2] + b0, c[mt][nt][3] + b1);
            *(float2*)&C[(size_t)row * N + col]       = v0;
            *(float2*)&C[(size_t)(row + 8) * N + col] = v1;
        }
    }
}

// ---------------------------------------------------------------------------
// Flash attention (fp32, causal + bool mask) — unchanged from passing round
// ---------------------------------------------------------------------------
#define BR 64
#define BC 64
#define PSTR 68

#define SM_QT   0
#define SM_KT   (DHEAD * PSTR)
#define SM_V    (SM_KT + DHEAD * PSTR)
#define SM_PT   (SM_V + BC * DHEAD)
#define SM_M    (SM_PT + BC * PSTR)
#define SM_L    (SM_M + BR)
#define SM_AL   (SM_L + BR)
#define SM_RED  (SM_AL + BR)
#define SM_MASK (SM_RED + 256)
#define ATTN_SMEM_BYTES ((SM_MASK) * 4 + BR * BC)

__global__ void __launch_bounds__(256, 1)
attn_kernel(const float* __restrict__ mixed,
            const unsigned char* __restrict__ mask,
            float* __restrict__ ctx)
{
    extern __shared__ float smf[];
    float* sQt = smf + SM_QT;
    float* sKt = smf + SM_KT;
    float* sV  = smf + SM_V;
    float* sPt = smf + SM_PT;
    float* sM  = smf + SM_M;
    float* sL  = smf + SM_L;
    float* sAl = smf + SM_AL;
    float* sRed = smf + SM_RED;
    unsigned char* sMask = (unsigned char*)(smf + SM_MASK);

    const int tid = threadIdx.x;
    const int q0 = blockIdx.x * BR;
    const int h  = blockIdx.y;
    const int b  = blockIdx.z;

    const size_t rowStride = (size_t)BATCH * QKV_N;
    const float* Qbase = mixed + (size_t)b * QKV_N + h * (3 * DHEAD);
    const float* Kbase = Qbase + DHEAD;
    const float* Vbase = Qbase + 2 * DHEAD;

    const int ty = tid >> 4;
    const int tx = tid & 15;

    for (int base = tid * 4; base < BR * DHEAD; base += 256 * 4) {
        int r = base / DHEAD, c = base % DHEAD;
        float4 v = *(const float4*)(Qbase + (size_t)(q0 + r) * rowStride + c);
        sQt[(c + 0) * PSTR + r] = v.x;
        sQt[(c + 1) * PSTR + r] = v.y;
        sQt[(c + 2) * PSTR + r] = v.z;
        sQt[(c + 3) * PSTR + r] = v.w;
    }
    if (tid < BR) { sM[tid] = -1e30f; sL[tid] = 0.0f; }

    float accO[4][8];
#pragma unroll
    for (int i = 0; i < 4; i++)
#pragma unroll
        for (int j = 0; j < 8; j++) accO[i][j] = 0.0f;

    __syncthreads();

    const int ntiles = blockIdx.x + 1;
    for (int t = 0; t < ntiles; t++) {
        const int k0 = t * BC;

        for (int base = tid * 4; base < BC * DHEAD; base += 256 * 4) {
            int r = base / DHEAD, c = base % DHEAD;
            float4 kv = *(const float4*)(Kbase + (size_t)(k0 + r) * rowStride + c);
            sKt[(c + 0) * PSTR + r] = kv.x;
            sKt[(c + 1) * PSTR + r] = kv.y;
            sKt[(c + 2) * PSTR + r] = kv.z;
            sKt[(c + 3) * PSTR + r] = kv.w;
            float4 vv = *(const float4*)(Vbase + (size_t)(k0 + r) * rowStride + c);
            *(float4*)&sV[r * DHEAD + c] = vv;
        }
        {
            const unsigned char* mb = mask + (size_t)b * S_LEN * S_LEN;
            int mr = tid >> 2, mc = (tid & 3) * 16;
            uint4 mv = *(const uint4*)(mb + (size_t)(q0 + mr) * S_LEN + k0 + mc);
            *(uint4*)&sMask[mr * BC + mc] = mv;
        }
        __syncthreads();

        {
            float s[4][4];
#pragma unroll
            for (int i = 0; i < 4; i++)
#pragma unroll
                for (int j = 0; j < 4; j++) s[i][j] = 0.0f;

#pragma unroll 4
            for (int kk = 0; kk < DHEAD; kk++) {
                float a[4], bb[4];
                *(float4*)a  = *(const float4*)&sQt[kk * PSTR + ty * 4];
                *(float4*)bb = *(const float4*)&sKt[kk * PSTR + tx * 4];
#pragma unroll
                for (int i = 0; i < 4; i++)
#pragma unroll
                    for (int j = 0; j < 4; j++)
                        s[i][j] = fmaf(a[i], bb[j], s[i][j]);
            }
            const float scale = 0.0883883476483184405f;
#pragma unroll
            for (int i = 0; i < 4; i++) {
                const int r = ty * 4 + i;
                const int qi = q0 + r;
#pragma unroll
                for (int j = 0; j < 4; j++) {
                    const int c = tx * 4 + j;
                    const int kj = k0 + c;
                    float val = s[i][j] * scale;
                    if (kj > qi || sMask[r * BC + c]) val = -10000.0f;
                    sPt[c * PSTR + r] = val;
                }
            }
        }
        __syncthreads();

        {
            const int r = tid & 63, ch = tid >> 6, cb = ch * 16;
            float mloc = -1e30f;
#pragma unroll
            for (int c = 0; c < 16; c++)
                mloc = fmaxf(mloc, sPt[(cb + c) * PSTR + r]);
            sRed[ch * 64 + r] = mloc;
        }
        __syncthreads();
        if (tid < BR) {
            float mnew = fmaxf(fmaxf(sRed[tid], sRed[64 + tid]),
                               fmaxf(sRed[128 + tid], sRed[192 + tid]));
            float mold = sM[tid];
            mnew = fmaxf(mold, mnew);
            float alpha = __expf(mold - mnew);
            sAl[tid] = alpha;
            sM[tid] = mnew;
            sL[tid] *= alpha;
        }
        __syncthreads();

        {
            const int r = tid & 63, ch = tid >> 6, cb = ch * 16;
            const float mnew = sM[r];
            float ssum = 0.0f;
#pragma unroll
            for (int c = 0; c < 16; c++) {
                float p = __expf(sPt[(cb + c) * PSTR + r] - mnew);
                sPt[(cb + c) * PSTR + r] = p;
                ssum += p;
            }
            sRed[ch * 64 + r] = ssum;
        }
        __syncthreads();
        if (tid < BR)
            sL[tid] += sRed[tid] + sRed[64 + tid] + sRed[128 + tid] + sRed[192 + tid];

        {
            float al[4];
#pragma unroll
            for (int i = 0; i < 4; i++) al[i] = sAl[ty * 4 + i];
#pragma unroll
            for (int i = 0; i < 4; i++)
#pragma unroll
                for (int j = 0; j < 8; j++) accO[i][j] *= al[i];

#pragma unroll 4
            for (int kk = 0; kk < BC; kk++) {
                float a[4], bv[8];
                *(float4*)a        = *(const float4*)&sPt[kk * PSTR + ty * 4];
                *(float4*)(bv)     = *(const float4*)&sV[kk * DHEAD + tx * 8];
                *(float4*)(bv + 4) = *(const float4*)&sV[kk * DHEAD + tx * 8 + 4];
#pragma unroll
                for (int i = 0; i < 4; i++)
#pragma unroll
                    for (int j = 0; j < 8; j++)
                        accO[i][j] = fmaf(a[i], bv[j], accO[i][j]);
            }
        }
        __syncthreads();
    }

#pragma unroll
    for (int i = 0; i < 4; i++) {
        const int r = ty * 4 + i;
        const float inv = 1.0f / sL[r];
        float* dst = ctx + ((size_t)(q0 + r) * BATCH + b) * HID + h * DHEAD + tx * 8;
        float4 v0, v1;
        v0.x = accO[i][0] * inv; v0.y = accO[i][1] * inv;
        v0.z = accO[i][2] * inv; v0.w = accO[i][3] * inv;
        v1.x = accO[i][4] * inv; v1.y = accO[i][5] * inv;
        v1.z = accO[i][6] * inv; v1.w = accO[i][7] * inv;
        *(float4*)(dst)     = v0;
        *(float4*)(dst + 4) = v1;
    }
}

__global__ void bias_tail_kernel(const float* __restrict__ proj_bias,
                                 float* __restrict__ out_tail)
{
    int i = blockIdx.x * blockDim.x + threadIdx.x;
    if (i < HID) out_tail[i] = proj_bias[i];
}

// ---------------------------------------------------------------------------
extern "C" void kernel_launch(void* const* d_in, const int* in_sizes, int n_in,
                              void* d_out, int out_size)
{
    const float* hidden      = (const float*)d_in[0];
    const unsigned char* msk = (const unsigned char*)d_in[1];
    const float* qkv_w       = (const float*)d_in[2];
    const float* qkv_b       = (const float*)d_in[3];
    const float* proj_w      = (const float*)d_in[4];
    const float* proj_b      = (const float*)d_in[5];
    float* out               = (float*)d_out;

    float *mixed, *ctx;
    __nv_bfloat16 *aHi, *aLo, *wqHi, *wqLo, *wpHi, *wpLo;
    cudaGetSymbolAddress((void**)&mixed, g_mixed);
    cudaGetSymbolAddress((void**)&ctx, g_ctx);
    cudaGetSymbolAddress((void**)&aHi, g_Ahi);
    cudaGetSymbolAddress((void**)&aLo, g_Alo);
    cudaGetSymbolAddress((void**)&wqHi, g_WqT_hi);
    cudaGetSymbolAddress((void**)&wqLo, g_WqT_lo);
    cudaGetSymbolAddress((void**)&wpHi, g_WpT_hi);
    cudaGetSymbolAddress((void**)&wpLo, g_WpT_lo);

    cudaFuncSetAttribute(attn_kernel,
                         cudaFuncAttributeMaxDynamicSharedMemorySize, ATTN_SMEM_BYTES);
    cudaFuncSetAttribute(gemm_mma_kernel,
                         cudaFuncAttributeMaxDynamicSharedMemorySize, G_SMEM_BYTES);

    // 0) Weight transpose + split, activation split
    {
        dim3 blk(32, 8);
        transpose_split_kernel<<<dim3(QKV_N / 32, HID / 32), blk>>>(qkv_w, wqHi, wqLo, HID, QKV_N);
        transpose_split_kernel<<<dim3(HID / 32, HID / 32), blk>>>(proj_w, wpHi, wpLo, HID, HID);
        int n4 = ROWS * HID / 4;
        split_kernel<<<(n4 + 255) / 256, 256>>>(hidden, aHi, aLo, n4);
    }
    // 1) QKV GEMM (HMMA split-bf16): mixed = hidden @ qkv_w + b
    {
        dim3 grid(QKV_N / 128, ROWS / 128);
        gemm_mma_kernel<<<grid, 256, G_SMEM_BYTES>>>(ROWS, QKV_N, HID,
                                                     aHi, aLo, wqHi, wqLo, qkv_b, mixed);
    }
    // 2) Flash attention -> ctx
    {
        dim3 grid(S_LEN / BR, NHEAD, BATCH);
        attn_kernel<<<grid, 256, ATTN_SMEM_BYTES>>>(mixed, msk, ctx);
    }
    // 3) Split ctx, then projection: out = ctx @ proj_w
    {
        int n4 = ROWS * HID / 4;
        split_kernel<<<(n4 + 255) / 256, 256>>>(ctx, aHi, aLo, n4);
        dim3 grid(HID / 128, ROWS / 128);
        gemm_mma_kernel<<<grid, 256, G_SMEM_BYTES>>>(ROWS, HID, HID,
                                                     aHi, aLo, wpHi, wpLo,
                                                     (const float*)nullptr, out);
    }
    // 4) Tail: proj_bias after main output
    bias_tail_kernel<<<(HID + 255) / 256, 256>>>(proj_b, out + (size_t)ROWS * HID);
}

// round 6
// speedup vs baseline: 3.1206x; 1.7375x over previous
#include <cuda_runtime.h>
#include <cuda_bf16.h>
#include <cstdint>

// Problem constants (fixed by setup_inputs)
#define S_LEN 2048
#define BATCH 2
#define HID   2048
#define NHEAD 16
#define DHEAD 128
#define QKV_N (3 * HID)          // 6144
#define ROWS  (S_LEN * BATCH)    // 4096
#define MROW  (BATCH * QKV_N)    // 12288: elements between consecutive s in mixed

// ---------------------------------------------------------------------------
// Scratch (no allocations allowed anywhere)
// ---------------------------------------------------------------------------
__device__ __nv_bfloat16 g_Mhi[(size_t)ROWS * QKV_N];     // mixed split hi
__device__ __nv_bfloat16 g_Mlo[(size_t)ROWS * QKV_N];     // mixed split lo
__device__ __nv_bfloat16 g_Ahi[(size_t)ROWS * HID];       // activation split (hidden, then ctx)
__device__ __nv_bfloat16 g_Alo[(size_t)ROWS * HID];
__device__ __nv_bfloat16 g_WqT_hi[(size_t)QKV_N * HID];   // qkv_w^T [6144,2048]
__device__ __nv_bfloat16 g_WqT_lo[(size_t)QKV_N * HID];
__device__ __nv_bfloat16 g_WpT_hi[(size_t)HID * HID];     // proj_w^T [2048,2048]
__device__ __nv_bfloat16 g_WpT_lo[(size_t)HID * HID];

// ---------------------------------------------------------------------------
// PTX helpers (sm_80-era features only — must assemble for plain sm_103)
// ---------------------------------------------------------------------------
__device__ __forceinline__ uint32_t smem_u32(const void* p) {
    uint32_t a;
    asm("{ .reg .u64 t; cvta.to.shared.u64 t, %1; cvt.u32.u64 %0, t; }"
        : "=r"(a) : "l"(p));
    return a;
}

#define CP_ASYNC16(dst, src) \
    asm volatile("cp.async.cg.shared.global [%0], [%1], 16;" \
        :: "r"(dst), "l"(src))
#define CP_COMMIT() asm volatile("cp.async.commit_group;" ::: "memory")
#define CP_WAIT1()  asm volatile("cp.async.wait_group 1;" ::: "memory")
#define CP_WAIT0()  asm volatile("cp.async.wait_group 0;" ::: "memory")

__device__ __forceinline__ void ldsm4(uint32_t* r, uint32_t addr) {
    asm volatile("ldmatrix.sync.aligned.m8n8.x4.shared.b16 {%0,%1,%2,%3}, [%4];"
        : "=r"(r[0]), "=r"(r[1]), "=r"(r[2]), "=r"(r[3]) : "r"(addr));
}
__device__ __forceinline__ void ldsm4t(uint32_t* r, uint32_t addr) {
    asm volatile("ldmatrix.sync.aligned.m8n8.x4.trans.shared.b16 {%0,%1,%2,%3}, [%4];"
        : "=r"(r[0]), "=r"(r[1]), "=r"(r[2]), "=r"(r[3]) : "r"(addr));
}

__device__ __forceinline__ void mma_bf16(float* c, const uint32_t* a, const uint32_t* b) {
    asm volatile(
        "mma.sync.aligned.m16n8k16.row.col.f32.bf16.bf16.f32 "
        "{%0,%1,%2,%3}, {%4,%5,%6,%7}, {%8,%9}, {%0,%1,%2,%3};"
        : "+f"(c[0]), "+f"(c[1]), "+f"(c[2]), "+f"(c[3])
        : "r"(a[0]), "r"(a[1]), "r"(a[2]), "r"(a[3]), "r"(b[0]), "r"(b[1]));
}

#define SMEM_SWIZZLE_128B(o) ((o) ^ (((o) >> 3) & 0x70))
// swizzle for tiles with 256-byte rows (128 bf16): XOR 16B-chunk idx with row%8
__device__ __forceinline__ uint32_t swz256(uint32_t r, uint32_t byte) {
    return r * 256 + (byte ^ ((r & 7) << 4));
}

// ---------------------------------------------------------------------------
// Conversion kernels
// ---------------------------------------------------------------------------
__global__ void split_kernel(const float* __restrict__ X,
                             __nv_bfloat16* __restrict__ hi,
                             __nv_bfloat16* __restrict__ lo, int n4)
{
    int i = blockIdx.x * blockDim.x + threadIdx.x;
    if (i >= n4) return;
    float4 v = ((const float4*)X)[i];
    __nv_bfloat16 h0 = __float2bfloat16(v.x), h1 = __float2bfloat16(v.y);
    __nv_bfloat16 h2 = __float2bfloat16(v.z), h3 = __float2bfloat16(v.w);
    __nv_bfloat16 l0 = __float2bfloat16(v.x - __bfloat162float(h0));
    __nv_bfloat16 l1 = __float2bfloat16(v.y - __bfloat162float(h1));
    __nv_bfloat16 l2 = __float2bfloat16(v.z - __bfloat162float(h2));
    __nv_bfloat16 l3 = __float2bfloat16(v.w - __bfloat162float(h3));
    ((__nv_bfloat162*)hi)[i * 2]     = __halves2bfloat162(h0, h1);
    ((__nv_bfloat162*)hi)[i * 2 + 1] = __halves2bfloat162(h2, h3);
    ((__nv_bfloat162*)lo)[i * 2]     = __halves2bfloat162(l0, l1);
    ((__nv_bfloat162*)lo)[i * 2 + 1] = __halves2bfloat162(l2, l3);
}

// W [K,N] fp32 -> hi/lo [N,K] bf16 (transpose + split)
__global__ void transpose_split_kernel(const float* __restrict__ W,
                                       __nv_bfloat16* __restrict__ hi,
                                       __nv_bfloat16* __restrict__ lo,
                                       int K, int N)
{
    __shared__ float t[32][33];
    int n0 = blockIdx.x * 32, k0 = blockIdx.y * 32;
    int tx = threadIdx.x, ty = threadIdx.y;  // 32 x 8
#pragma unroll
    for (int i = 0; i < 32; i += 8)
        t[ty + i][tx] = W[(size_t)(k0 + ty + i) * N + n0 + tx];
    __syncthreads();
#pragma unroll
    for (int i = 0; i < 32; i += 8) {
        int n = n0 + ty + i;
        int k = k0 + tx;
        float v = t[tx][ty + i];   // = W[k][n]
        __nv_bfloat16 h = __float2bfloat16(v);
        hi[(size_t)n * K + k] = h;
        lo[(size_t)n * K + k] = __float2bfloat16(v - __bfloat162float(h));
    }
}

// ---------------------------------------------------------------------------
// HMMA split-bf16 GEMM: C = A @ Bt^T (+bias). Optionally writes split-bf16
// output (outHi/outLo) instead of fp32 C.
// ---------------------------------------------------------------------------
#define G_STAGE 65536                 // Ahi|Alo|Bhi|Blo, 16KB each
#define G_SMEM_BYTES (3 * G_STAGE + 1024)

__global__ void __launch_bounds__(256, 1)
gemm_mma_kernel(int M, int N, int K,
                const __nv_bfloat16* __restrict__ Ahi,
                const __nv_bfloat16* __restrict__ Alo,
                const __nv_bfloat16* __restrict__ Bhi,
                const __nv_bfloat16* __restrict__ Blo,
                const float* __restrict__ bias,
                float* __restrict__ C,
                __nv_bfloat16* __restrict__ outHi,
                __nv_bfloat16* __restrict__ outLo)
{
    extern __shared__ char smraw[];
    uint32_t sraw = smem_u32(smraw);
    const uint32_t sb = (sraw + 1023u) & ~1023u;

    const int tid  = threadIdx.x;
    const int lane = tid & 31;
    const int warp = tid >> 5;
    const int wm = warp & 3;
    const int wn = warp >> 2;
    const int rowBase = blockIdx.y * 128;
    const int colBase = blockIdx.x * 128;

    const int nch = K >> 6;

    auto load_stage = [&](int stage, int k0) {
        const uint32_t sBase = sb + stage * G_STAGE;
#pragma unroll
        for (int tIdx = 0; tIdx < 4; tIdx++) {
            const __nv_bfloat16* src =
                (tIdx == 0) ? Ahi : (tIdx == 1) ? Alo : (tIdx == 2) ? Bhi : Blo;
            const int rb = (tIdx < 2) ? rowBase : colBase;
#pragma unroll
            for (int i = 0; i < 4; i++) {
                int s = tid + i * 256;
                int r = s >> 3, c16 = s & 7;
                const void* g = src + (size_t)(rb + r) * K + k0 + c16 * 8;
                uint32_t d = sBase + tIdx * 16384 + SMEM_SWIZZLE_128B(r * 128 + c16 * 16);
                CP_ASYNC16(d, g);
            }
        }
    };

    float c[2][8][4];
#pragma unroll
    for (int mt = 0; mt < 2; mt++)
#pragma unroll
        for (int nt = 0; nt < 8; nt++)
#pragma unroll
            for (int j = 0; j < 4; j++) c[mt][nt][j] = 0.0f;

    load_stage(0, 0);
    CP_COMMIT();
    load_stage(1, 64);
    CP_COMMIT();

    const int aRow  = wm * 32 + (lane & 15);
    const int aKoff = (lane >> 4) << 4;
    const int bRow  = wn * 64 + (lane & 7) + ((lane >> 4) << 3);
    const int bKoff = ((lane >> 3) & 1) << 4;

    for (int ch = 0; ch < nch; ch++) {
        CP_WAIT1();
        __syncthreads();
        if (ch + 2 < nch) {
            load_stage((ch + 2) % 3, (ch + 2) << 6);
            CP_COMMIT();
        } else {
            CP_COMMIT();
        }

        const uint32_t sA_hi = sb + (ch % 3) * G_STAGE;
        const uint32_t sA_lo = sA_hi + 16384;
        const uint32_t sB_hi = sA_hi + 32768;
        const uint32_t sB_lo = sA_hi + 49152;

#pragma unroll
        for (int ks = 0; ks < 4; ks++) {
            uint32_t aH[2][4], aL[2][4];
            const int kbA = ks * 32 + aKoff;
#pragma unroll
            for (int mt = 0; mt < 2; mt++) {
                uint32_t off = SMEM_SWIZZLE_128B((aRow + mt * 16) * 128 + kbA);
                ldsm4(aH[mt], sA_hi + off);
                ldsm4(aL[mt], sA_lo + off);
            }
            uint32_t bH[4][4], bL[4][4];
            const int kbB = ks * 32 + bKoff;
#pragma unroll
            for (int nt = 0; nt < 4; nt++) {
                uint32_t off = SMEM_SWIZZLE_128B((bRow + nt * 16) * 128 + kbB);
                ldsm4(bH[nt], sB_hi + off);
                ldsm4(bL[nt], sB_lo + off);
            }
#pragma unroll
            for (int mt = 0; mt < 2; mt++)
#pragma unroll
                for (int nt = 0; nt < 4; nt++) {
                    mma_bf16(c[mt][nt * 2],     aH[mt], &bH[nt][0]);
                    mma_bf16(c[mt][nt * 2],     aH[mt], &bL[nt][0]);
                    mma_bf16(c[mt][nt * 2],     aL[mt], &bH[nt][0]);
                    mma_bf16(c[mt][nt * 2 + 1], aH[mt], &bH[nt][2]);
                    mma_bf16(c[mt][nt * 2 + 1], aH[mt], &bL[nt][2]);
                    mma_bf16(c[mt][nt * 2 + 1], aL[mt], &bH[nt][2]);
                }
        }
        __syncthreads();
    }

    const int qr = lane >> 2;
    const int qc = (lane & 3) * 2;
#pragma unroll
    for (int mt = 0; mt < 2; mt++) {
        const int row = rowBase + wm * 32 + mt * 16 + qr;
#pragma unroll
        for (int nt = 0; nt < 8; nt++) {
            const int col = colBase + wn * 64 + nt * 8 + qc;
            float b0 = 0.0f, b1 = 0.0f;
            if (bias) { b0 = bias[col]; b1 = bias[col + 1]; }
            float v00 = c[mt][nt][0] + b0, v01 = c[mt][nt][1] + b1;
            float v10 = c[mt][nt][2] + b0, v11 = c[mt][nt][3] + b1;
            if (outHi) {
                __nv_bfloat16 h00 = __float2bfloat16(v00), h01 = __float2bfloat16(v01);
                __nv_bfloat16 h10 = __float2bfloat16(v10), h11 = __float2bfloat16(v11);
                __nv_bfloat16 l00 = __float2bfloat16(v00 - __bfloat162float(h00));
                __nv_bfloat16 l01 = __float2bfloat16(v01 - __bfloat162float(h01));
                __nv_bfloat16 l10 = __float2bfloat16(v10 - __bfloat162float(h10));
                __nv_bfloat16 l11 = __float2bfloat16(v11 - __bfloat162float(h11));
                *(__nv_bfloat162*)&outHi[(size_t)row * N + col]       = __halves2bfloat162(h00, h01);
                *(__nv_bfloat162*)&outHi[(size_t)(row + 8) * N + col] = __halves2bfloat162(h10, h11);
                *(__nv_bfloat162*)&outLo[(size_t)row * N + col]       = __halves2bfloat162(l00, l01);
                *(__nv_bfloat162*)&outLo[(size_t)(row + 8) * N + col] = __halves2bfloat162(l10, l11);
            } else {
                *(float2*)&C[(size_t)row * N + col]       = make_float2(v00, v01);
                *(float2*)&C[(size_t)(row + 8) * N + col] = make_float2(v10, v11);
            }
        }
    }
}

// ---------------------------------------------------------------------------
// HMMA flash attention: 128q x 64k tiles, split-bf16 QK^T and PV,
// smem softmax, causal + bool mask. 256 threads, 8 warps (4m x 2n).
// ---------------------------------------------------------------------------
#define SSTR 66                       // sS row stride in floats (bank-safe)
// byte offsets in dynamic smem (after 1KB alignment)
#define A_OQH   0
#define A_OQL   32768
#define A_OKH   65536
#define A_OKL   81920
#define A_OVH   98304
#define A_OVL   114688
#define A_OS    131072                // 128 x 66 fp32 = 33792
#define A_OPH   164864                // 16384
#define A_OPL   181248                // 16384
#define A_OMASK 197632                // 8192
#define A_OM    205824                // 512
#define A_OL    206336
#define A_OAL   206848
#define A_ORED  207360                // 1024
#define A_TOTAL 208384
#define ATTN_SMEM_BYTES (A_TOTAL + 1024)

__global__ void __launch_bounds__(256, 1)
attn_mma_kernel(const __nv_bfloat16* __restrict__ Mhi,
                const __nv_bfloat16* __restrict__ Mlo,
                const unsigned char* __restrict__ mask,
                __nv_bfloat16* __restrict__ ctxHi,
                __nv_bfloat16* __restrict__ ctxLo)
{
    extern __shared__ char smraw[];
    uint32_t sraw = smem_u32(smraw);
    const uint32_t sb = (sraw + 1023u) & ~1023u;
    char* smc = smraw + (sb - sraw);

    float* sS   = (float*)(smc + A_OS);
    float* sM   = (float*)(smc + A_OM);
    float* sL   = (float*)(smc + A_OL);
    float* sAl  = (float*)(smc + A_OAL);
    float* sRed = (float*)(smc + A_ORED);
    unsigned char* sMask = (unsigned char*)(smc + A_OMASK);

    const int tid  = threadIdx.x;
    const int lane = tid & 31;
    const int warp = tid >> 5;
    const int wm = warp & 3;
    const int wn = warp >> 2;

    const int qt = (gridDim.x - 1) - blockIdx.x;   // heavy blocks first
    const int q0 = qt * 128;
    const int h  = blockIdx.y;
    const int b  = blockIdx.z;
    const size_t headOff = (size_t)b * QKV_N + h * (3 * DHEAD);

    // ---- load Q hi/lo (cp.async, swizzled 256B rows) ----
#pragma unroll
    for (int i = 0; i < 16; i++) {
        int s = tid + i * 256;          // 0..4095
        int half = s >> 11;             // 0: hi, 1: lo
        int s2 = s & 2047;
        int r = s2 >> 4, c16 = s2 & 15;
        const __nv_bfloat16* src = (half ? Mlo : Mhi) +
            (size_t)(q0 + r) * MROW + headOff + c16 * 8;
        uint32_t d = sb + (half ? A_OQL : A_OQH) + swz256(r, c16 * 16);
        CP_ASYNC16(d, src);
    }
    CP_COMMIT();

    if (tid < 128) { sM[tid] = -1e30f; sL[tid] = 0.0f; }

    float accO[2][8][4];
#pragma unroll
    for (int mt = 0; mt < 2; mt++)
#pragma unroll
        for (int nt = 0; nt < 8; nt++)
#pragma unroll
            for (int j = 0; j < 4; j++) accO[mt][nt][j] = 0.0f;

    const int qr = lane >> 2;
    const int qc = (lane & 3) * 2;
    const float scale = 0.0883883476483184405f;   // 1/sqrt(128)

    const int ntiles = 2 * qt + 2;
    for (int t = 0; t < ntiles; t++) {
        const int k0 = t * 64;

        // ---- load K,V hi/lo (cp.async) ----
#pragma unroll
        for (int i = 0; i < 16; i++) {
            int s = tid + i * 256;      // 0..4095
            int ts = s >> 10;           // 0:Khi 1:Klo 2:Vhi 3:Vlo
            int s2 = s & 1023;
            int r = s2 >> 4, c16 = s2 & 15;
            const __nv_bfloat16* src = ((ts & 1) ? Mlo : Mhi) +
                (size_t)(k0 + r) * MROW + headOff + ((ts < 2) ? DHEAD : 2 * DHEAD) + c16 * 8;
            uint32_t d = sb + A_OKH + ts * 16384 + swz256(r, c16 * 16);
            CP_ASYNC16(d, src);
        }
        CP_COMMIT();
        // ---- mask tile (regular loads) ----
        {
            const unsigned char* mb = mask + (size_t)b * S_LEN * S_LEN;
            int mr = tid >> 1, mc = (tid & 1) * 32;
            const uint4* src = (const uint4*)(mb + (size_t)(q0 + mr) * S_LEN + k0 + mc);
            uint4 v0 = src[0], v1 = src[1];
            *(uint4*)&sMask[mr * 64 + mc]      = v0;
            *(uint4*)&sMask[mr * 64 + mc + 16] = v1;
        }
        CP_WAIT0();
        __syncthreads();

        // ================= QK^T (split-bf16 HMMA) =================
        float s_[2][4][4];
#pragma unroll
        for (int mt = 0; mt < 2; mt++)
#pragma unroll
            for (int nt = 0; nt < 4; nt++)
#pragma unroll
                for (int j = 0; j < 4; j++) s_[mt][nt][j] = 0.0f;

#pragma unroll
        for (int ks = 0; ks < 8; ks++) {
            uint32_t aH[2][4], aL[2][4];
            const uint32_t aByte = ks * 32 + ((lane >> 4) << 4);
#pragma unroll
            for (int mt = 0; mt < 2; mt++) {
                uint32_t off = swz256(wm * 32 + mt * 16 + (lane & 15), aByte);
                ldsm4(aH[mt], sb + A_OQH + off);
                ldsm4(aL[mt], sb + A_OQL + off);
            }
            const uint32_t bByte = ks * 32 + (((lane >> 3) & 1) << 4);
#pragma unroll
            for (int half = 0; half < 2; half++) {
                uint32_t bh[4], bl[4];
                uint32_t off = swz256(wn * 32 + half * 16 + (lane & 7) + ((lane >> 4) << 3), bByte);
                ldsm4(bh, sb + A_OKH + off);
                ldsm4(bl, sb + A_OKL + off);
#pragma unroll
                for (int mt = 0; mt < 2; mt++) {
                    mma_bf16(s_[mt][half * 2],     aH[mt], &bh[0]);
                    mma_bf16(s_[mt][half * 2],     aH[mt], &bl[0]);
                    mma_bf16(s_[mt][half * 2],     aL[mt], &bh[0]);
                    mma_bf16(s_[mt][half * 2 + 1], aH[mt], &bh[2]);
                    mma_bf16(s_[mt][half * 2 + 1], aH[mt], &bl[2]);
                    mma_bf16(s_[mt][half * 2 + 1], aL[mt], &bh[2]);
                }
            }
        }
        // scale + causal + mask, store to sS
#pragma unroll
        for (int mt = 0; mt < 2; mt++) {
#pragma unroll
            for (int nt = 0; nt < 4; nt++) {
                const int c = wn * 32 + nt * 8 + qc;
                const int r0 = wm * 32 + mt * 16 + qr;
                const int r1 = r0 + 8;
                float v00 = s_[mt][nt][0] * scale, v01 = s_[mt][nt][1] * scale;
                float v10 = s_[mt][nt][2] * scale, v11 = s_[mt][nt][3] * scale;
                if (k0 + c     > q0 + r0 || sMask[r0 * 64 + c])     v00 = -10000.0f;
                if (k0 + c + 1 > q0 + r0 || sMask[r0 * 64 + c + 1]) v01 = -10000.0f;
                if (k0 + c     > q0 + r1 || sMask[r1 * 64 + c])     v10 = -10000.0f;
                if (k0 + c + 1 > q0 + r1 || sMask[r1 * 64 + c + 1]) v11 = -10000.0f;
                *(float2*)&sS[r0 * SSTR + c] = make_float2(v00, v01);
                *(float2*)&sS[r1 * SSTR + c] = make_float2(v10, v11);
            }
        }
        __syncthreads();

        // ================= softmax =================
        {
            const int r = tid & 127, ch = tid >> 7, cb = ch * 32;
            float mloc = -1e30f;
#pragma unroll
            for (int cc = 0; cc < 32; cc++)
                mloc = fmaxf(mloc, sS[r * SSTR + cb + cc]);
            sRed[ch * 128 + r] = mloc;
        }
        __syncthreads();
        if (tid < 128) {
            float mnew = fmaxf(sRed[tid], sRed[128 + tid]);
            float mold = sM[tid];
            mnew = fmaxf(mold, mnew);
            float alpha = __expf(mold - mnew);
            sAl[tid] = alpha;
            sM[tid] = mnew;
            sL[tid] *= alpha;
        }
        __syncthreads();
        {
            const int r = tid & 127, ch = tid >> 7, cb = ch * 32;
            const float mnew = sM[r];
            float ssum = 0.0f;
            uint32_t pBaseH = sb + A_OPH;
            uint32_t pBaseL = sb + A_OPL;
#pragma unroll
            for (int cc = 0; cc < 32; cc += 2) {
                float p0 = __expf(sS[r * SSTR + cb + cc]     - mnew);
                float p1 = __expf(sS[r * SSTR + cb + cc + 1] - mnew);
                ssum += p0 + p1;
                __nv_bfloat16 h0 = __float2bfloat16(p0), h1 = __float2bfloat16(p1);
                __nv_bfloat16 l0 = __float2bfloat16(p0 - __bfloat162float(h0));
                __nv_bfloat16 l1 = __float2bfloat16(p1 - __bfloat162float(h1));
                uint32_t off = SMEM_SWIZZLE_128B((uint32_t)(r * 128 + (cb + cc) * 2));
                __nv_bfloat162 hv = __halves2bfloat162(h0, h1);
                __nv_bfloat162 lv = __halves2bfloat162(l0, l1);
                asm volatile("st.shared.b32 [%0], %1;" :: "r"(pBaseH + off),
                             "r"(*(uint32_t*)&hv) : "memory");
                asm volatile("st.shared.b32 [%0], %1;" :: "r"(pBaseL + off),
                             "r"(*(uint32_t*)&lv) : "memory");
            }
            sRed[ch * 128 + r] = ssum;
        }
        __syncthreads();
        if (tid < 128)
            sL[tid] += sRed[tid] + sRed[128 + tid];
        __syncthreads();

        // ================= P @ V (split-bf16 HMMA) =================
        {
            const float al0 = sAl[wm * 32 + qr];
            const float al1 = sAl[wm * 32 + qr + 8];
            const float al2 = sAl[wm * 32 + 16 + qr];
            const float al3 = sAl[wm * 32 + 16 + qr + 8];
#pragma unroll
            for (int nt = 0; nt < 8; nt++) {
                accO[0][nt][0] *= al0; accO[0][nt][1] *= al0;
                accO[0][nt][2] *= al1; accO[0][nt][3] *= al1;
                accO[1][nt][0] *= al2; accO[1][nt][1] *= al2;
                accO[1][nt][2] *= al3; accO[1][nt][3] *= al3;
            }
        }
        {
            const int lr = lane & 7, mi = lane >> 3;
#pragma unroll
            for (int ks = 0; ks < 4; ks++) {
                uint32_t pH[2][4], pL[2][4];
                const uint32_t pByte = ks * 32 + ((lane >> 4) << 4);
#pragma unroll
                for (int mt = 0; mt < 2; mt++) {
                    uint32_t off = SMEM_SWIZZLE_128B(
                        (uint32_t)((wm * 32 + mt * 16 + (lane & 15)) * 128) + pByte);
                    ldsm4(pH[mt], sb + A_OPH + off);
                    ldsm4(pL[mt], sb + A_OPL + off);
                }
#pragma unroll
                for (int np = 0; np < 4; np++) {
                    uint32_t vh[4], vl[4];
                    uint32_t vrow = ks * 16 + ((mi & 1) << 3) + lr;
                    uint32_t vbyte = (wn * 64 + np * 16) * 2 + ((mi >> 1) << 4);
                    uint32_t off = swz256(vrow, vbyte);
                    ldsm4t(vh, sb + A_OVH + off);
                    ldsm4t(vl, sb + A_OVL + off);
#pragma unroll
                    for (int mt = 0; mt < 2; mt++) {
                        mma_bf16(accO[mt][np * 2],     pH[mt], &vh[0]);
                        mma_bf16(accO[mt][np * 2],     pH[mt], &vl[0]);
                        mma_bf16(accO[mt][np * 2],     pL[mt], &vh[0]);
                        mma_bf16(accO[mt][np * 2 + 1], pH[mt], &vh[2]);
                        mma_bf16(accO[mt][np * 2 + 1], pH[mt], &vl[2]);
                        mma_bf16(accO[mt][np * 2 + 1], pL[mt], &vh[2]);
                    }
                }
            }
        }
        __syncthreads();   // protect sK/sV/sS/sP before next tile's loads
    }

    // ---- epilogue: O/l -> split bf16 ctx ----
#pragma unroll
    for (int mt = 0; mt < 2; mt++) {
        const int lr0 = wm * 32 + mt * 16 + qr;
        const float inv0 = 1.0f / sL[lr0];
        const float inv1 = 1.0f / sL[lr0 + 8];
        const size_t base0 = ((size_t)(q0 + lr0) * BATCH + b) * HID + h * DHEAD;
        const size_t base1 = ((size_t)(q0 + lr0 + 8) * BATCH + b) * HID + h * DHEAD;
#pragma unroll
        for (int nt = 0; nt < 8; nt++) {
            const int col = wn * 64 + nt * 8 + qc;
            float v00 = accO[mt][nt][0] * inv0, v01 = accO[mt][nt][1] * inv0;
            float v10 = accO[mt][nt][2] * inv1, v11 = accO[mt][nt][3] * inv1;
            __nv_bfloat16 h00 = __float2bfloat16(v00), h01 = __float2bfloat16(v01);
            __nv_bfloat16 h10 = __float2bfloat16(v10), h11 = __float2bfloat16(v11);
            __nv_bfloat16 l00 = __float2bfloat16(v00 - __bfloat162float(h00));
            __nv_bfloat16 l01 = __float2bfloat16(v01 - __bfloat162float(h01));
            __nv_bfloat16 l10 = __float2bfloat16(v10 - __bfloat162float(h10));
            __nv_bfloat16 l11 = __float2bfloat16(v11 - __bfloat162float(h11));
            *(__nv_bfloat162*)&ctxHi[base0 + col] = __halves2bfloat162(h00, h01);
            *(__nv_bfloat162*)&ctxHi[base1 + col] = __halves2bfloat162(h10, h11);
            *(__nv_bfloat162*)&ctxLo[base0 + col] = __halves2bfloat162(l00, l01);
            *(__nv_bfloat162*)&ctxLo[base1 + col] = __halves2bfloat162(l10, l11);
        }
    }
}

__global__ void bias_tail_kernel(const float* __restrict__ proj_bias,
                                 float* __restrict__ out_tail)
{
    int i = blockIdx.x * blockDim.x + threadIdx.x;
    if (i < HID) out_tail[i] = proj_bias[i];
}

// ---------------------------------------------------------------------------
extern "C" void kernel_launch(void* const* d_in, const int* in_sizes, int n_in,
                              void* d_out, int out_size)
{
    const float* hidden      = (const float*)d_in[0];
    const unsigned char* msk = (const unsigned char*)d_in[1];
    const float* qkv_w       = (const float*)d_in[2];
    const float* qkv_b       = (const float*)d_in[3];
    const float* proj_w      = (const float*)d_in[4];
    const float* proj_b      = (const float*)d_in[5];
    float* out               = (float*)d_out;

    __nv_bfloat16 *mHi, *mLo, *aHi, *aLo, *wqHi, *wqLo, *wpHi, *wpLo;
    cudaGetSymbolAddress((void**)&mHi, g_Mhi);
    cudaGetSymbolAddress((void**)&mLo, g_Mlo);
    cudaGetSymbolAddress((void**)&aHi, g_Ahi);
    cudaGetSymbolAddress((void**)&aLo, g_Alo);
    cudaGetSymbolAddress((void**)&wqHi, g_WqT_hi);
    cudaGetSymbolAddress((void**)&wqLo, g_WqT_lo);
    cudaGetSymbolAddress((void**)&wpHi, g_WpT_hi);
    cudaGetSymbolAddress((void**)&wpLo, g_WpT_lo);

    cudaFuncSetAttribute(attn_mma_kernel,
                         cudaFuncAttributeMaxDynamicSharedMemorySize, ATTN_SMEM_BYTES);
    cudaFuncSetAttribute(gemm_mma_kernel,
                         cudaFuncAttributeMaxDynamicSharedMemorySize, G_SMEM_BYTES);

    // 0) Weight transpose + split, activation split
    {
        dim3 blk(32, 8);
        transpose_split_kernel<<<dim3(QKV_N / 32, HID / 32), blk>>>(qkv_w, wqHi, wqLo, HID, QKV_N);
        transpose_split_kernel<<<dim3(HID / 32, HID / 32), blk>>>(proj_w, wpHi, wpLo, HID, HID);
        int n4 = ROWS * HID / 4;
        split_kernel<<<(n4 + 255) / 256, 256>>>(hidden, aHi, aLo, n4);
    }
    // 1) QKV GEMM -> split-bf16 mixed (fused: no fp32 roundtrip)
    {
        dim3 grid(QKV_N / 128, ROWS / 128);
        gemm_mma_kernel<<<grid, 256, G_SMEM_BYTES>>>(ROWS, QKV_N, HID,
                                                     aHi, aLo, wqHi, wqLo, qkv_b,
                                                     nullptr, mHi, mLo);
    }
    // 2) HMMA flash attention -> split-bf16 ctx (into proj input buffers)
    {
        dim3 grid(S_LEN / 128, NHEAD, BATCH);
        attn_mma_kernel<<<grid, 256, ATTN_SMEM_BYTES>>>(mHi, mLo, msk, aHi, aLo);
    }
    // 3) Projection: out = ctx @ proj_w (fp32 out)
    {
        dim3 grid(HID / 128, ROWS / 128);
        gemm_mma_kernel<<<grid, 256, G_SMEM_BYTES>>>(ROWS, HID, HID,
                                                     aHi, aLo, wpHi, wpLo,
                                                     (const float*)nullptr, out,
                                                     nullptr, nullptr);
    }
    // 4) Tail: proj_bias after main output
    bias_tail_kernel<<<(HID + 255) / 256, 256>>>(proj_b, out + (size_t)ROWS * HID);
}

// round 8
// speedup vs baseline: 3.4915x; 1.1188x over previous
#include <cuda_runtime.h>
#include <cuda_bf16.h>
#include <cstdint>

// Problem constants (fixed by setup_inputs)
#define S_LEN 2048
#define BATCH 2
#define HID   2048
#define NHEAD 16
#define DHEAD 128
#define QKV_N (3 * HID)          // 6144
#define ROWS  (S_LEN * BATCH)    // 4096
#define MROW  (BATCH * QKV_N)    // 12288: elements between consecutive s in mixed

// ---------------------------------------------------------------------------
// Scratch (no allocations allowed anywhere)
// ---------------------------------------------------------------------------
__device__ __nv_bfloat16 g_Mhi[(size_t)ROWS * QKV_N];     // mixed split hi
__device__ __nv_bfloat16 g_Mlo[(size_t)ROWS * QKV_N];     // mixed split lo
__device__ __nv_bfloat16 g_Ahi[(size_t)ROWS * HID];       // activation split (hidden, then ctx)
__device__ __nv_bfloat16 g_Alo[(size_t)ROWS * HID];
__device__ __nv_bfloat16 g_WqT_hi[(size_t)QKV_N * HID];   // qkv_w^T [6144,2048]
__device__ __nv_bfloat16 g_WqT_lo[(size_t)QKV_N * HID];
__device__ __nv_bfloat16 g_WpT_hi[(size_t)HID * HID];     // proj_w^T [2048,2048]
__device__ __nv_bfloat16 g_WpT_lo[(size_t)HID * HID];

// ---------------------------------------------------------------------------
// PTX helpers (sm_80-era features only — must assemble for plain sm_103)
// ---------------------------------------------------------------------------
__device__ __forceinline__ uint32_t smem_u32(const void* p) {
    uint32_t a;
    asm("{ .reg .u64 t; cvta.to.shared.u64 t, %1; cvt.u32.u64 %0, t; }"
        : "=r"(a) : "l"(p));
    return a;
}

#define CP_ASYNC16(dst, src) \
    asm volatile("cp.async.cg.shared.global [%0], [%1], 16;" \
        :: "r"(dst), "l"(src))
#define CP_COMMIT() asm volatile("cp.async.commit_group;" ::: "memory")
#define CP_WAIT1()  asm volatile("cp.async.wait_group 1;" ::: "memory")
#define CP_WAIT0()  asm volatile("cp.async.wait_group 0;" ::: "memory")

__device__ __forceinline__ void ldsm4(uint32_t* r, uint32_t addr) {
    asm volatile("ldmatrix.sync.aligned.m8n8.x4.shared.b16 {%0,%1,%2,%3}, [%4];"
        : "=r"(r[0]), "=r"(r[1]), "=r"(r[2]), "=r"(r[3]) : "r"(addr));
}
__device__ __forceinline__ void ldsm4t(uint32_t* r, uint32_t addr) {
    asm volatile("ldmatrix.sync.aligned.m8n8.x4.trans.shared.b16 {%0,%1,%2,%3}, [%4];"
        : "=r"(r[0]), "=r"(r[1]), "=r"(r[2]), "=r"(r[3]) : "r"(addr));
}

__device__ __forceinline__ void mma_bf16(float* c, const uint32_t* a, const uint32_t* b) {
    asm volatile(
        "mma.sync.aligned.m16n8k16.row.col.f32.bf16.bf16.f32 "
        "{%0,%1,%2,%3}, {%4,%5,%6,%7}, {%8,%9}, {%0,%1,%2,%3};"
        : "+f"(c[0]), "+f"(c[1]), "+f"(c[2]), "+f"(c[3])
        : "r"(a[0]), "r"(a[1]), "r"(a[2]), "r"(a[3]), "r"(b[0]), "r"(b[1]));
}

#define SMEM_SWIZZLE_128B(o) ((o) ^ (((o) >> 3) & 0x70))
// swizzle for tiles with 256-byte rows (128 bf16): XOR 16B-chunk idx with row%8
__device__ __forceinline__ uint32_t swz256(uint32_t r, uint32_t byte) {
    return r * 256 + (byte ^ ((r & 7) << 4));
}

// ---------------------------------------------------------------------------
// Conversion kernels
// ---------------------------------------------------------------------------
__global__ void split_kernel(const float* __restrict__ X,
                             __nv_bfloat16* __restrict__ hi,
                             __nv_bfloat16* __restrict__ lo, int n4)
{
    int i = blockIdx.x * blockDim.x + threadIdx.x;
    if (i >= n4) return;
    float4 v = ((const float4*)X)[i];
    __nv_bfloat16 h0 = __float2bfloat16(v.x), h1 = __float2bfloat16(v.y);
    __nv_bfloat16 h2 = __float2bfloat16(v.z), h3 = __float2bfloat16(v.w);
    __nv_bfloat16 l0 = __float2bfloat16(v.x - __bfloat162float(h0));
    __nv_bfloat16 l1 = __float2bfloat16(v.y - __bfloat162float(h1));
    __nv_bfloat16 l2 = __float2bfloat16(v.z - __bfloat162float(h2));
    __nv_bfloat16 l3 = __float2bfloat16(v.w - __bfloat162float(h3));
    ((__nv_bfloat162*)hi)[i * 2]     = __halves2bfloat162(h0, h1);
    ((__nv_bfloat162*)hi)[i * 2 + 1] = __halves2bfloat162(h2, h3);
    ((__nv_bfloat162*)lo)[i * 2]     = __halves2bfloat162(l0, l1);
    ((__nv_bfloat162*)lo)[i * 2 + 1] = __halves2bfloat162(l2, l3);
}

// W [K,N] fp32 -> hi/lo [N,K] bf16 (transpose + split)
__global__ void transpose_split_kernel(const float* __restrict__ W,
                                       __nv_bfloat16* __restrict__ hi,
                                       __nv_bfloat16* __restrict__ lo,
                                       int K, int N)
{
    __shared__ float t[32][33];
    int n0 = blockIdx.x * 32, k0 = blockIdx.y * 32;
    int tx = threadIdx.x, ty = threadIdx.y;  // 32 x 8
#pragma unroll
    for (int i = 0; i < 32; i += 8)
        t[ty + i][tx] = W[(size_t)(k0 + ty + i) * N + n0 + tx];
    __syncthreads();
#pragma unroll
    for (int i = 0; i < 32; i += 8) {
        int n = n0 + ty + i;
        int k = k0 + tx;
        float v = t[tx][ty + i];   // = W[k][n]
        __nv_bfloat16 h = __float2bfloat16(v);
        hi[(size_t)n * K + k] = h;
        lo[(size_t)n * K + k] = __float2bfloat16(v - __bfloat162float(h));
    }
}

// ---------------------------------------------------------------------------
// HMMA split-bf16 GEMM: C = A @ Bt^T (+bias). Optionally writes split-bf16
// output (outHi/outLo) instead of fp32 C.
// MMA issue order is term-major: same-accumulator reuse distance = 16 issues
// (breaks the RAW chain that capped tensor util at 67%).
// ---------------------------------------------------------------------------
#define G_STAGE 65536                 // Ahi|Alo|Bhi|Blo, 16KB each
#define G_SMEM_BYTES (3 * G_STAGE + 1024)

__global__ void __launch_bounds__(256, 1)
gemm_mma_kernel(int M, int N, int K,
                const __nv_bfloat16* __restrict__ Ahi,
                const __nv_bfloat16* __restrict__ Alo,
                const __nv_bfloat16* __restrict__ Bhi,
                const __nv_bfloat16* __restrict__ Blo,
                const float* __restrict__ bias,
                float* __restrict__ C,
                __nv_bfloat16* __restrict__ outHi,
                __nv_bfloat16* __restrict__ outLo)
{
    extern __shared__ char smraw[];
    uint32_t sraw = smem_u32(smraw);
    const uint32_t sb = (sraw + 1023u) & ~1023u;

    const int tid  = threadIdx.x;
    const int lane = tid & 31;
    const int warp = tid >> 5;
    const int wm = warp & 3;
    const int wn = warp >> 2;
    const int rowBase = blockIdx.y * 128;
    const int colBase = blockIdx.x * 128;

    const int nch = K >> 6;

    auto load_stage = [&](int stage, int k0) {
        const uint32_t sBase = sb + stage * G_STAGE;
#pragma unroll
        for (int tIdx = 0; tIdx < 4; tIdx++) {
            const __nv_bfloat16* src =
                (tIdx == 0) ? Ahi : (tIdx == 1) ? Alo : (tIdx == 2) ? Bhi : Blo;
            const int rb = (tIdx < 2) ? rowBase : colBase;
#pragma unroll
            for (int i = 0; i < 4; i++) {
                int s = tid + i * 256;
                int r = s >> 3, c16 = s & 7;
                const void* g = src + (size_t)(rb + r) * K + k0 + c16 * 8;
                uint32_t d = sBase + tIdx * 16384 + SMEM_SWIZZLE_128B(r * 128 + c16 * 16);
                CP_ASYNC16(d, g);
            }
        }
    };

    float c[2][8][4];
#pragma unroll
    for (int mt = 0; mt < 2; mt++)
#pragma unroll
        for (int nt = 0; nt < 8; nt++)
#pragma unroll
            for (int j = 0; j < 4; j++) c[mt][nt][j] = 0.0f;

    load_stage(0, 0);
    CP_COMMIT();
    load_stage(1, 64);
    CP_COMMIT();

    const int aRow  = wm * 32 + (lane & 15);
    const int aKoff = (lane >> 4) << 4;
    const int bRow  = wn * 64 + (lane & 7) + ((lane >> 4) << 3);
    const int bKoff = ((lane >> 3) & 1) << 4;

    for (int ch = 0; ch < nch; ch++) {
        CP_WAIT1();
        __syncthreads();
        if (ch + 2 < nch) {
            load_stage((ch + 2) % 3, (ch + 2) << 6);
            CP_COMMIT();
        } else {
            CP_COMMIT();
        }

        const uint32_t sA_hi = sb + (ch % 3) * G_STAGE;
        const uint32_t sA_lo = sA_hi + 16384;
        const uint32_t sB_hi = sA_hi + 32768;
        const uint32_t sB_lo = sA_hi + 49152;

#pragma unroll
        for (int ks = 0; ks < 4; ks++) {
            uint32_t aH[2][4], aL[2][4];
            const int kbA = ks * 32 + aKoff;
#pragma unroll
            for (int mt = 0; mt < 2; mt++) {
                uint32_t off = SMEM_SWIZZLE_128B((aRow + mt * 16) * 128 + kbA);
                ldsm4(aH[mt], sA_hi + off);
                ldsm4(aL[mt], sA_lo + off);
            }
            uint32_t bH[4][4], bL[4][4];
            const int kbB = ks * 32 + bKoff;
#pragma unroll
            for (int nt = 0; nt < 4; nt++) {
                uint32_t off = SMEM_SWIZZLE_128B((bRow + nt * 16) * 128 + kbB);
                ldsm4(bH[nt], sB_hi + off);
                ldsm4(bL[nt], sB_lo + off);
            }
            // term-major issue order: 16-issue gap between same-acc MMAs
#pragma unroll
            for (int mt = 0; mt < 2; mt++)
#pragma unroll
                for (int nt = 0; nt < 4; nt++) {
                    mma_bf16(c[mt][nt * 2],     aH[mt], &bH[nt][0]);
                    mma_bf16(c[mt][nt * 2 + 1], aH[mt], &bH[nt][2]);
                }
#pragma unroll
            for (int mt = 0; mt < 2; mt++)
#pragma unroll
                for (int nt = 0; nt < 4; nt++) {
                    mma_bf16(c[mt][nt * 2],     aH[mt], &bL[nt][0]);
                    mma_bf16(c[mt][nt * 2 + 1], aH[mt], &bL[nt][2]);
                }
#pragma unroll
            for (int mt = 0; mt < 2; mt++)
#pragma unroll
                for (int nt = 0; nt < 4; nt++) {
                    mma_bf16(c[mt][nt * 2],     aL[mt], &bH[nt][0]);
                    mma_bf16(c[mt][nt * 2 + 1], aL[mt], &bH[nt][2]);
                }
        }
        __syncthreads();
    }

    const int qr = lane >> 2;
    const int qc = (lane & 3) * 2;
#pragma unroll
    for (int mt = 0; mt < 2; mt++) {
        const int row = rowBase + wm * 32 + mt * 16 + qr;
#pragma unroll
        for (int nt = 0; nt < 8; nt++) {
            const int col = colBase + wn * 64 + nt * 8 + qc;
            float b0 = 0.0f, b1 = 0.0f;
            if (bias) { b0 = bias[col]; b1 = bias[col + 1]; }
            float v00 = c[mt][nt][0] + b0, v01 = c[mt][nt][1] + b1;
            float v10 = c[mt][nt][2] + b0, v11 = c[mt][nt][3] + b1;
            if (outHi) {
                __nv_bfloat16 h00 = __float2bfloat16(v00), h01 = __float2bfloat16(v01);
                __nv_bfloat16 h10 = __float2bfloat16(v10), h11 = __float2bfloat16(v11);
                __nv_bfloat16 l00 = __float2bfloat16(v00 - __bfloat162float(h00));
                __nv_bfloat16 l01 = __float2bfloat16(v01 - __bfloat162float(h01));
                __nv_bfloat16 l10 = __float2bfloat16(v10 - __bfloat162float(h10));
                __nv_bfloat16 l11 = __float2bfloat16(v11 - __bfloat162float(h11));
                *(__nv_bfloat162*)&outHi[(size_t)row * N + col]       = __halves2bfloat162(h00, h01);
                *(__nv_bfloat162*)&outHi[(size_t)(row + 8) * N + col] = __halves2bfloat162(h10, h11);
                *(__nv_bfloat162*)&outLo[(size_t)row * N + col]       = __halves2bfloat162(l00, l01);
                *(__nv_bfloat162*)&outLo[(size_t)(row + 8) * N + col] = __halves2bfloat162(l10, l11);
            } else {
                *(float2*)&C[(size_t)row * N + col]       = make_float2(v00, v01);
                *(float2*)&C[(size_t)(row + 8) * N + col] = make_float2(v10, v11);
            }
        }
    }
}

// ---------------------------------------------------------------------------
// FA2-style HMMA flash attention: 128q x 64k tiles, 8 warps x 16 rows each,
// register-resident softmax (quad shuffles), P fed to PV straight from regs,
// double-buffered K/V/mask via cp.async. Split-bf16 (3-term) both MMAs.
// ---------------------------------------------------------------------------
// smem byte offsets (from 1KB-aligned base)
#define A_OQH   0                     // Q hi: 128 x 256B = 32KB
#define A_OQL   32768                 // Q lo: 32KB
#define A_OKV   65536                 // 2 stages x 64KB: KH|KL|VH|VL (16KB each)
#define A_OMSK  196608                // 2 stages x 8KB mask
#define ATTN_SMEM_BYTES (212992 + 1024)

__global__ void __launch_bounds__(256, 1)
attn_mma_kernel(const __nv_bfloat16* __restrict__ Mhi,
                const __nv_bfloat16* __restrict__ Mlo,
                const unsigned char* __restrict__ mask,
                __nv_bfloat16* __restrict__ ctxHi,
                __nv_bfloat16* __restrict__ ctxLo)
{
    extern __shared__ char smraw[];
    uint32_t sraw = smem_u32(smraw);
    const uint32_t sb = (sraw + 1023u) & ~1023u;
    char* smc = smraw + (sb - sraw);

    const int tid  = threadIdx.x;
    const int lane = tid & 31;
    const int warp = tid >> 5;            // 0..7, owns rows warp*16..+15
    const int gr   = lane >> 2;           // 0..7 row-in-group
    const int tg   = lane & 3;            // quad col group
    const int qc   = tg * 2;

    const int qt = (gridDim.x - 1) - blockIdx.x;   // heavy blocks first
    const int q0 = qt * 128;
    const int h  = blockIdx.y;
    const int b  = blockIdx.z;
    const size_t headOff = (size_t)b * QKV_N + h * (3 * DHEAD);
    const unsigned char* mb = mask + (size_t)b * S_LEN * S_LEN;

    // ---- issue Q hi/lo loads (own commit group) ----
#pragma unroll
    for (int i = 0; i < 16; i++) {
        int s = tid + i * 256;          // 0..4095
        int half = s >> 11;
        int s2 = s & 2047;
        int r = s2 >> 4, c16 = s2 & 15;
        const __nv_bfloat16* src = (half ? Mlo : Mhi) +
            (size_t)(q0 + r) * MROW + headOff + c16 * 8;
        uint32_t d = sb + (half ? A_OQL : A_OQH) + swz256(r, c16 * 16);
        CP_ASYNC16(d, src);
    }
    CP_COMMIT();

    auto issue_kv = [&](int stage, int t) {
        const int k0 = t * 64;
        const uint32_t kvb = sb + A_OKV + stage * 65536;
#pragma unroll
        for (int i = 0; i < 16; i++) {
            int s = tid + i * 256;      // 0..4095
            int ts = s >> 10;           // 0:KH 1:KL 2:VH 3:VL
            int s2 = s & 1023;
            int r = s2 >> 4, c16 = s2 & 15;
            const __nv_bfloat16* src = ((ts & 1) ? Mlo : Mhi) +
                (size_t)(k0 + r) * MROW + headOff + ((ts < 2) ? DHEAD : 2 * DHEAD) + c16 * 8;
            CP_ASYNC16(kvb + ts * 16384 + swz256(r, c16 * 16), src);
        }
        const uint32_t mkb = sb + A_OMSK + stage * 8192;
#pragma unroll
        for (int i = 0; i < 2; i++) {
            int cid = tid + i * 256;    // 0..511
            int r = cid >> 2, c16 = cid & 3;
            const void* src = mb + (size_t)(q0 + r) * S_LEN + t * 64 + c16 * 16;
            CP_ASYNC16(mkb + r * 64 + c16 * 16, src);
        }
    };

    issue_kv(0, 0);
    CP_COMMIT();

    float accO[16][4];
#pragma unroll
    for (int nt = 0; nt < 16; nt++)
#pragma unroll
        for (int j = 0; j < 4; j++) accO[nt][j] = 0.0f;

    float m0 = -1e30f, m1 = -1e30f, l0 = 0.0f, l1 = 0.0f;
    const float scale = 0.0883883476483184405f;   // 1/sqrt(128)
    const int lr = lane & 7, mi = lane >> 3;

    const int ntiles = 2 * qt + 2;
    for (int t = 0; t < ntiles; t++) {
        const int st = t & 1;
        if (t + 1 < ntiles) issue_kv((t + 1) & 1, t + 1);
        CP_COMMIT();
        CP_WAIT1();
        __syncthreads();

        const uint32_t sKH = sb + A_OKV + st * 65536;
        const uint32_t sKL = sKH + 16384;
        const uint32_t sVH = sKH + 32768;
        const uint32_t sVL = sKH + 49152;
        const uint32_t sMsk = sb + A_OMSK + st * 8192;
        const int k0 = t * 64;

        // ================= QK^T =================
        float s_[8][4];
#pragma unroll
        for (int nt = 0; nt < 8; nt++)
#pragma unroll
            for (int j = 0; j < 4; j++) s_[nt][j] = 0.0f;

#pragma unroll
        for (int ks = 0; ks < 8; ks++) {
            uint32_t aH[4], aL[4];
            {
                uint32_t off = swz256(warp * 16 + (lane & 15),
                                      ks * 32 + ((lane >> 4) << 4));
                ldsm4(aH, sb + A_OQH + off);
                ldsm4(aL, sb + A_OQL + off);
            }
            uint32_t bH[4][4], bL[4][4];
            const uint32_t bByte = ks * 32 + (((lane >> 3) & 1) << 4);
#pragma unroll
            for (int p = 0; p < 4; p++) {
                uint32_t off = swz256(p * 16 + (lane & 7) + ((lane >> 4) << 3), bByte);
                ldsm4(bH[p], sKH + off);
                ldsm4(bL[p], sKL + off);
            }
            // term-major: 8-issue same-acc gap
#pragma unroll
            for (int p = 0; p < 4; p++) {
                mma_bf16(s_[p * 2],     aH, &bH[p][0]);
                mma_bf16(s_[p * 2 + 1], aH, &bH[p][2]);
            }
#pragma unroll
            for (int p = 0; p < 4; p++) {
                mma_bf16(s_[p * 2],     aH, &bL[p][0]);
                mma_bf16(s_[p * 2 + 1], aH, &bL[p][2]);
            }
#pragma unroll
            for (int p = 0; p < 4; p++) {
                mma_bf16(s_[p * 2],     aL, &bH[p][0]);
                mma_bf16(s_[p * 2 + 1], aL, &bH[p][2]);
            }
        }

        // ---- scale + padding mask + (causal on diagonal tiles) ----
        const int r0 = q0 + warp * 16 + gr;
        const int r1 = r0 + 8;
        const bool diag = (t >= 2 * qt);
#pragma unroll
        for (int nt = 0; nt < 8; nt++) {
            const int c = nt * 8 + qc;
            unsigned short mpair0, mpair1;
            asm volatile("ld.shared.u16 %0, [%1];" : "=h"(mpair0)
                         : "r"(sMsk + (warp * 16 + gr) * 64 + c));
            asm volatile("ld.shared.u16 %0, [%1];" : "=h"(mpair1)
                         : "r"(sMsk + (warp * 16 + gr + 8) * 64 + c));
            float v0 = s_[nt][0] * scale, v1 = s_[nt][1] * scale;
            float v2 = s_[nt][2] * scale, v3 = s_[nt][3] * scale;
            if (mpair0 & 0x00FF) v0 = -10000.0f;
            if (mpair0 & 0xFF00) v1 = -10000.0f;
            if (mpair1 & 0x00FF) v2 = -10000.0f;
            if (mpair1 & 0xFF00) v3 = -10000.0f;
            if (diag) {
                if (k0 + c     > r0) v0 = -10000.0f;
                if (k0 + c + 1 > r0) v1 = -10000.0f;
                if (k0 + c     > r1) v2 = -10000.0f;
                if (k0 + c + 1 > r1) v3 = -10000.0f;
            }
            s_[nt][0] = v0; s_[nt][1] = v1; s_[nt][2] = v2; s_[nt][3] = v3;
        }

        // ---- row max (registers + quad shuffles) ----
        float mx0 = -1e30f, mx1 = -1e30f;
#pragma unroll
        for (int nt = 0; nt < 8; nt++) {
            mx0 = fmaxf(mx0, fmaxf(s_[nt][0], s_[nt][1]));
            mx1 = fmaxf(mx1, fmaxf(s_[nt][2], s_[nt][3]));
        }
        mx0 = fmaxf(mx0, __shfl_xor_sync(0xffffffffu, mx0, 1));
        mx0 = fmaxf(mx0, __shfl_xor_sync(0xffffffffu, mx0, 2));
        mx1 = fmaxf(mx1, __shfl_xor_sync(0xffffffffu, mx1, 1));
        mx1 = fmaxf(mx1, __shfl_xor_sync(0xffffffffu, mx1, 2));

        const float mn0 = fmaxf(m0, mx0);
        const float mn1 = fmaxf(m1, mx1);
        const float al0 = __expf(m0 - mn0);
        const float al1 = __expf(m1 - mn1);
        m0 = mn0; m1 = mn1;

        // ---- exp + row sums ----
        float sm0 = 0.0f, sm1 = 0.0f;
#pragma unroll
        for (int nt = 0; nt < 8; nt++) {
            float p0 = __expf(s_[nt][0] - mn0);
            float p1 = __expf(s_[nt][1] - mn0);
            float p2 = __expf(s_[nt][2] - mn1);
            float p3 = __expf(s_[nt][3] - mn1);
            sm0 += p0 + p1; sm1 += p2 + p3;
            s_[nt][0] = p0; s_[nt][1] = p1; s_[nt][2] = p2; s_[nt][3] = p3;
        }
        sm0 += __shfl_xor_sync(0xffffffffu, sm0, 1);
        sm0 += __shfl_xor_sync(0xffffffffu, sm0, 2);
        sm1 += __shfl_xor_sync(0xffffffffu, sm1, 1);
        sm1 += __shfl_xor_sync(0xffffffffu, sm1, 2);
        l0 = l0 * al0 + sm0;
        l1 = l1 * al1 + sm1;

        // ---- rescale accO ----
#pragma unroll
        for (int nt = 0; nt < 16; nt++) {
            accO[nt][0] *= al0; accO[nt][1] *= al0;
            accO[nt][2] *= al1; accO[nt][3] *= al1;
        }

        // ================= P @ V (P from registers) =================
#pragma unroll
        for (int ks = 0; ks < 4; ks++) {
            // A-frags for keys ks*16..+15 from P register split
            uint32_t pH[4], pL[4];
            {
                const float* e0 = s_[2 * ks];
                const float* e1 = s_[2 * ks + 1];
                __nv_bfloat16 h00 = __float2bfloat16(e0[0]), h01 = __float2bfloat16(e0[1]);
                __nv_bfloat16 h02 = __float2bfloat16(e0[2]), h03 = __float2bfloat16(e0[3]);
                __nv_bfloat16 h10 = __float2bfloat16(e1[0]), h11 = __float2bfloat16(e1[1]);
                __nv_bfloat16 h12 = __float2bfloat16(e1[2]), h13 = __float2bfloat16(e1[3]);
                __nv_bfloat162 a0 = __halves2bfloat162(h00, h01);
                __nv_bfloat162 a1 = __halves2bfloat162(h02, h03);
                __nv_bfloat162 a2 = __halves2bfloat162(h10, h11);
                __nv_bfloat162 a3 = __halves2bfloat162(h12, h13);
                pH[0] = *(uint32_t*)&a0; pH[1] = *(uint32_t*)&a1;
                pH[2] = *(uint32_t*)&a2; pH[3] = *(uint32_t*)&a3;
                __nv_bfloat16 g00 = __float2bfloat16(e0[0] - __bfloat162float(h00));
                __nv_bfloat16 g01 = __float2bfloat16(e0[1] - __bfloat162float(h01));
                __nv_bfloat16 g02 = __float2bfloat16(e0[2] - __bfloat162float(h02));
                __nv_bfloat16 g03 = __float2bfloat16(e0[3] - __bfloat162float(h03));
                __nv_bfloat16 g10 = __float2bfloat16(e1[0] - __bfloat162float(h10));
                __nv_bfloat16 g11 = __float2bfloat16(e1[1] - __bfloat162float(h11));
                __nv_bfloat16 g12 = __float2bfloat16(e1[2] - __bfloat162float(h12));
                __nv_bfloat16 g13 = __float2bfloat16(e1[3] - __bfloat162float(h13));
                __nv_bfloat162 c0 = __halves2bfloat162(g00, g01);
                __nv_bfloat162 c1 = __halves2bfloat162(g02, g03);
                __nv_bfloat162 c2 = __halves2bfloat162(g10, g11);
                __nv_bfloat162 c3 = __halves2bfloat162(g12, g13);
                pL[0] = *(uint32_t*)&c0; pL[1] = *(uint32_t*)&c1;
                pL[2] = *(uint32_t*)&c2; pL[3] = *(uint32_t*)&c3;
            }
            const uint32_t vrow = ks * 16 + ((mi & 1) << 3) + lr;
            // two halves of 4 np each to bound live registers
#pragma unroll
            for (int hh = 0; hh < 2; hh++) {
                uint32_t vh[4][4], vl[4][4];
#pragma unroll
                for (int np = 0; np < 4; np++) {
                    uint32_t vbyte = (hh * 4 + np) * 32 + ((mi >> 1) << 4);
                    uint32_t off = swz256(vrow, vbyte);
                    ldsm4t(vh[np], sVH + off);
                    ldsm4t(vl[np], sVL + off);
                }
                float (*aO)[4] = &accO[hh * 8];
#pragma unroll
                for (int np = 0; np < 4; np++) {
                    mma_bf16(aO[np * 2],     pH, &vh[np][0]);
                    mma_bf16(aO[np * 2 + 1], pH, &vh[np][2]);
                }
#pragma unroll
                for (int np = 0; np < 4; np++) {
                    mma_bf16(aO[np * 2],     pH, &vl[np][0]);
                    mma_bf16(aO[np * 2 + 1], pH, &vl[np][2]);
                }
#pragma unroll
                for (int np = 0; np < 4; np++) {
                    mma_bf16(aO[np * 2],     pL, &vh[np][0]);
                    mma_bf16(aO[np * 2 + 1], pL, &vh[np][2]);
                }
            }
        }
        __syncthreads();   // all warps done with this stage's K/V/mask
    }

    // ---- epilogue: O/l -> split bf16 ctx ----
    const float inv0 = 1.0f / l0;
    const float inv1 = 1.0f / l1;
    const int row0 = q0 + warp * 16 + gr;
    const size_t base0 = ((size_t)row0 * BATCH + b) * HID + h * DHEAD;
    const size_t base1 = ((size_t)(row0 + 8) * BATCH + b) * HID + h * DHEAD;
#pragma unroll
    for (int nt = 0; nt < 16; nt++) {
        const int col = nt * 8 + qc;
        float v00 = accO[nt][0] * inv0, v01 = accO[nt][1] * inv0;
        float v10 = accO[nt][2] * inv1, v11 = accO[nt][3] * inv1;
        __nv_bfloat16 h00 = __float2bfloat16(v00), h01 = __float2bfloat16(v01);
        __nv_bfloat16 h10 = __float2bfloat16(v10), h11 = __float2bfloat16(v11);
        __nv_bfloat16 l00 = __float2bfloat16(v00 - __bfloat162float(h00));
        __nv_bfloat16 l01 = __float2bfloat16(v01 - __bfloat162float(h01));
        __nv_bfloat16 l10 = __float2bfloat16(v10 - __bfloat162float(h10));
        __nv_bfloat16 l11 = __float2bfloat16(v11 - __bfloat162float(h11));
        *(__nv_bfloat162*)&ctxHi[base0 + col] = __halves2bfloat162(h00, h01);
        *(__nv_bfloat162*)&ctxHi[base1 + col] = __halves2bfloat162(h10, h11);
        *(__nv_bfloat162*)&ctxLo[base0 + col] = __halves2bfloat162(l00, l01);
        *(__nv_bfloat162*)&ctxLo[base1 + col] = __halves2bfloat162(l10, l11);
    }
}

__global__ void bias_tail_kernel(const float* __restrict__ proj_bias,
                                 float* __restrict__ out_tail)
{
    int i = blockIdx.x * blockDim.x + threadIdx.x;
    if (i < HID) out_tail[i] = proj_bias[i];
}

// ---------------------------------------------------------------------------
extern "C" void kernel_launch(void* const* d_in, const int* in_sizes, int n_in,
                              void* d_out, int out_size)
{
    const float* hidden      = (const float*)d_in[0];
    const unsigned char* msk = (const unsigned char*)d_in[1];
    const float* qkv_w       = (const float*)d_in[2];
    const float* qkv_b       = (const float*)d_in[3];
    const float* proj_w      = (const float*)d_in[4];
    const float* proj_b      = (const float*)d_in[5];
    float* out               = (float*)d_out;

    __nv_bfloat16 *mHi, *mLo, *aHi, *aLo, *wqHi, *wqLo, *wpHi, *wpLo;
    cudaGetSymbolAddress((void**)&mHi, g_Mhi);
    cudaGetSymbolAddress((void**)&mLo, g_Mlo);
    cudaGetSymbolAddress((void**)&aHi, g_Ahi);
    cudaGetSymbolAddress((void**)&aLo, g_Alo);
    cudaGetSymbolAddress((void**)&wqHi, g_WqT_hi);
    cudaGetSymbolAddress((void**)&wqLo, g_WqT_lo);
    cudaGetSymbolAddress((void**)&wpHi, g_WpT_hi);
    cudaGetSymbolAddress((void**)&wpLo, g_WpT_lo);

    cudaFuncSetAttribute(attn_mma_kernel,
                         cudaFuncAttributeMaxDynamicSharedMemorySize, ATTN_SMEM_BYTES);
    cudaFuncSetAttribute(gemm_mma_kernel,
                         cudaFuncAttributeMaxDynamicSharedMemorySize, G_SMEM_BYTES);

    // 0) Weight transpose + split, activation split
    {
        dim3 blk(32, 8);
        transpose_split_kernel<<<dim3(QKV_N / 32, HID / 32), blk>>>(qkv_w, wqHi, wqLo, HID, QKV_N);
        transpose_split_kernel<<<dim3(HID / 32, HID / 32), blk>>>(proj_w, wpHi, wpLo, HID, HID);
        int n4 = ROWS * HID / 4;
        split_kernel<<<(n4 + 255) / 256, 256>>>(hidden, aHi, aLo, n4);
    }
    // 1) QKV GEMM -> split-bf16 mixed
    {
        dim3 grid(QKV_N / 128, ROWS / 128);
        gemm_mma_kernel<<<grid, 256, G_SMEM_BYTES>>>(ROWS, QKV_N, HID,
                                                     aHi, aLo, wqHi, wqLo, qkv_b,
                                                     nullptr, mHi, mLo);
    }
    // 2) FA2 HMMA attention -> split-bf16 ctx (into proj input buffers)
    {
        dim3 grid(S_LEN / 128, NHEAD, BATCH);
        attn_mma_kernel<<<grid, 256, ATTN_SMEM_BYTES>>>(mHi, mLo, msk, aHi, aLo);
    }
    // 3) Projection: out = ctx @ proj_w (fp32 out)
    {
        dim3 grid(HID / 128, ROWS / 128);
        gemm_mma_kernel<<<grid, 256, G_SMEM_BYTES>>>(ROWS, HID, HID,
                                                     aHi, aLo, wpHi, wpLo,
                                                     (const float*)nullptr, out,
                                                     nullptr, nullptr);
    }
    // 4) Tail: proj_bias after main output
    bias_tail_kernel<<<(HID + 255) / 256, 256>>>(proj_b, out + (size_t)ROWS * HID);
}

// round 9
// speedup vs baseline: 3.5630x; 1.0205x over previous
#include <cuda_runtime.h>
#include <cuda_bf16.h>
#include <cstdint>

// Problem constants (fixed by setup_inputs)
#define S_LEN 2048
#define BATCH 2
#define HID   2048
#define NHEAD 16
#define DHEAD 128
#define QKV_N (3 * HID)          // 6144
#define ROWS  (S_LEN * BATCH)    // 4096
#define MROW  (BATCH * QKV_N)    // 12288: elements between consecutive s in mixed

// ---------------------------------------------------------------------------
// Scratch (no allocations allowed anywhere)
// ---------------------------------------------------------------------------
__device__ __nv_bfloat16 g_Mhi[(size_t)ROWS * QKV_N];     // mixed split hi
__device__ __nv_bfloat16 g_Mlo[(size_t)ROWS * QKV_N];     // mixed split lo
__device__ __nv_bfloat16 g_Ahi[(size_t)ROWS * HID];       // activation split (hidden, then ctx)
__device__ __nv_bfloat16 g_Alo[(size_t)ROWS * HID];
__device__ __nv_bfloat16 g_WqT_hi[(size_t)QKV_N * HID];   // qkv_w^T [6144,2048]
__device__ __nv_bfloat16 g_WqT_lo[(size_t)QKV_N * HID];
__device__ __nv_bfloat16 g_WpT_hi[(size_t)HID * HID];     // proj_w^T [2048,2048]
__device__ __nv_bfloat16 g_WpT_lo[(size_t)HID * HID];

// ---------------------------------------------------------------------------
// PTX helpers (sm_80-era features only — must assemble for plain sm_103)
// ---------------------------------------------------------------------------
__device__ __forceinline__ uint32_t smem_u32(const void* p) {
    uint32_t a;
    asm("{ .reg .u64 t; cvta.to.shared.u64 t, %1; cvt.u32.u64 %0, t; }"
        : "=r"(a) : "l"(p));
    return a;
}

#define CP_ASYNC16(dst, src) \
    asm volatile("cp.async.cg.shared.global [%0], [%1], 16;" \
        :: "r"(dst), "l"(src))
#define CP_COMMIT() asm volatile("cp.async.commit_group;" ::: "memory")
#define CP_WAIT1()  asm volatile("cp.async.wait_group 1;" ::: "memory")
#define CP_WAIT0()  asm volatile("cp.async.wait_group 0;" ::: "memory")

__device__ __forceinline__ void ldsm4(uint32_t* r, uint32_t addr) {
    asm volatile("ldmatrix.sync.aligned.m8n8.x4.shared.b16 {%0,%1,%2,%3}, [%4];"
        : "=r"(r[0]), "=r"(r[1]), "=r"(r[2]), "=r"(r[3]) : "r"(addr));
}
__device__ __forceinline__ void ldsm4t(uint32_t* r, uint32_t addr) {
    asm volatile("ldmatrix.sync.aligned.m8n8.x4.trans.shared.b16 {%0,%1,%2,%3}, [%4];"
        : "=r"(r[0]), "=r"(r[1]), "=r"(r[2]), "=r"(r[3]) : "r"(addr));
}

__device__ __forceinline__ void mma_bf16(float* c, const uint32_t* a, const uint32_t* b) {
    asm volatile(
        "mma.sync.aligned.m16n8k16.row.col.f32.bf16.bf16.f32 "
        "{%0,%1,%2,%3}, {%4,%5,%6,%7}, {%8,%9}, {%0,%1,%2,%3};"
        : "+f"(c[0]), "+f"(c[1]), "+f"(c[2]), "+f"(c[3])
        : "r"(a[0]), "r"(a[1]), "r"(a[2]), "r"(a[3]), "r"(b[0]), "r"(b[1]));
}

#define SMEM_SWIZZLE_128B(o) ((o) ^ (((o) >> 3) & 0x70))
// swizzle for tiles with 256-byte rows (128 bf16): XOR 16B-chunk idx with row%8
__device__ __forceinline__ uint32_t swz256(uint32_t r, uint32_t byte) {
    return r * 256 + (byte ^ ((r & 7) << 4));
}

// ---------------------------------------------------------------------------
// Conversion kernels
// ---------------------------------------------------------------------------
__global__ void split_kernel(const float* __restrict__ X,
                             __nv_bfloat16* __restrict__ hi,
                             __nv_bfloat16* __restrict__ lo, int n4)
{
    int i = blockIdx.x * blockDim.x + threadIdx.x;
    if (i >= n4) return;
    float4 v = ((const float4*)X)[i];
    __nv_bfloat16 h0 = __float2bfloat16(v.x), h1 = __float2bfloat16(v.y);
    __nv_bfloat16 h2 = __float2bfloat16(v.z), h3 = __float2bfloat16(v.w);
    __nv_bfloat16 l0 = __float2bfloat16(v.x - __bfloat162float(h0));
    __nv_bfloat16 l1 = __float2bfloat16(v.y - __bfloat162float(h1));
    __nv_bfloat16 l2 = __float2bfloat16(v.z - __bfloat162float(h2));
    __nv_bfloat16 l3 = __float2bfloat16(v.w - __bfloat162float(h3));
    ((__nv_bfloat162*)hi)[i * 2]     = __halves2bfloat162(h0, h1);
    ((__nv_bfloat162*)hi)[i * 2 + 1] = __halves2bfloat162(h2, h3);
    ((__nv_bfloat162*)lo)[i * 2]     = __halves2bfloat162(l0, l1);
    ((__nv_bfloat162*)lo)[i * 2 + 1] = __halves2bfloat162(l2, l3);
}

// W [K,N] fp32 -> hi/lo [N,K] bf16 (transpose + split)
__global__ void transpose_split_kernel(const float* __restrict__ W,
                                       __nv_bfloat16* __restrict__ hi,
                                       __nv_bfloat16* __restrict__ lo,
                                       int K, int N)
{
    __shared__ float t[32][33];
    int n0 = blockIdx.x * 32, k0 = blockIdx.y * 32;
    int tx = threadIdx.x, ty = threadIdx.y;  // 32 x 8
#pragma unroll
    for (int i = 0; i < 32; i += 8)
        t[ty + i][tx] = W[(size_t)(k0 + ty + i) * N + n0 + tx];
    __syncthreads();
#pragma unroll
    for (int i = 0; i < 32; i += 8) {
        int n = n0 + ty + i;
        int k = k0 + tx;
        float v = t[tx][ty + i];   // = W[k][n]
        __nv_bfloat16 h = __float2bfloat16(v);
        hi[(size_t)n * K + k] = h;
        lo[(size_t)n * K + k] = __float2bfloat16(v - __bfloat162float(h));
    }
}

// ---------------------------------------------------------------------------
// HMMA split-bf16 GEMM: C = A @ Bt^T (+bias). Optionally writes split-bf16
// output (outHi/outLo) instead of fp32 C.
// 512 threads / 16 warps (4x4 warp grid), warp tile 32x32: 4 warps per SMSP
// to hide ldmatrix->MMA latency (2 warps/SMSP capped tensor util at 67%).
// One __syncthreads per chunk (3-stage rotation makes trailing barrier
// redundant: loads after the wait-barrier target the stage read 2 chunks ago).
// ---------------------------------------------------------------------------
#define G_STAGE 65536                 // Ahi|Alo|Bhi|Blo, 16KB each
#define G_SMEM_BYTES (3 * G_STAGE + 1024)

__global__ void __launch_bounds__(512, 1)
gemm_mma_kernel(int M, int N, int K,
                const __nv_bfloat16* __restrict__ Ahi,
                const __nv_bfloat16* __restrict__ Alo,
                const __nv_bfloat16* __restrict__ Bhi,
                const __nv_bfloat16* __restrict__ Blo,
                const float* __restrict__ bias,
                float* __restrict__ C,
                __nv_bfloat16* __restrict__ outHi,
                __nv_bfloat16* __restrict__ outLo)
{
    extern __shared__ char smraw[];
    uint32_t sraw = smem_u32(smraw);
    const uint32_t sb = (sraw + 1023u) & ~1023u;

    const int tid  = threadIdx.x;
    const int lane = tid & 31;
    const int warp = tid >> 5;        // 0..15
    const int wm = warp & 3;          // M group (rows wm*32..+31)
    const int wn = warp >> 2;         // N group (cols wn*32..+31)
    const int rowBase = blockIdx.y * 128;
    const int colBase = blockIdx.x * 128;

    const int nch = K >> 6;

    auto load_stage = [&](int stage, int k0) {
        const uint32_t sBase = sb + stage * G_STAGE;
#pragma unroll
        for (int tIdx = 0; tIdx < 4; tIdx++) {
            const __nv_bfloat16* src =
                (tIdx == 0) ? Ahi : (tIdx == 1) ? Alo : (tIdx == 2) ? Bhi : Blo;
            const int rb = (tIdx < 2) ? rowBase : colBase;
#pragma unroll
            for (int i = 0; i < 2; i++) {
                int s = tid + i * 512;       // 0..1023
                int r = s >> 3, c16 = s & 7;
                const void* g = src + (size_t)(rb + r) * K + k0 + c16 * 8;
                uint32_t d = sBase + tIdx * 16384 + SMEM_SWIZZLE_128B(r * 128 + c16 * 16);
                CP_ASYNC16(d, g);
            }
        }
    };

    float c[2][4][4];
#pragma unroll
    for (int mt = 0; mt < 2; mt++)
#pragma unroll
        for (int nt = 0; nt < 4; nt++)
#pragma unroll
            for (int j = 0; j < 4; j++) c[mt][nt][j] = 0.0f;

    load_stage(0, 0);
    CP_COMMIT();
    load_stage(1, 64);
    CP_COMMIT();

    const int aRow  = wm * 32 + (lane & 15);
    const int aKoff = (lane >> 4) << 4;
    const int bRow  = wn * 32 + (lane & 7) + ((lane >> 4) << 3);
    const int bKoff = ((lane >> 3) & 1) << 4;

    for (int ch = 0; ch < nch; ch++) {
        CP_WAIT1();
        __syncthreads();
        if (ch + 2 < nch) {
            load_stage((ch + 2) % 3, (ch + 2) << 6);
            CP_COMMIT();
        } else {
            CP_COMMIT();
        }

        const uint32_t sA_hi = sb + (ch % 3) * G_STAGE;
        const uint32_t sA_lo = sA_hi + 16384;
        const uint32_t sB_hi = sA_hi + 32768;
        const uint32_t sB_lo = sA_hi + 49152;

#pragma unroll
        for (int ks = 0; ks < 4; ks++) {
            uint32_t aH[2][4], aL[2][4];
            const int kbA = ks * 32 + aKoff;
#pragma unroll
            for (int mt = 0; mt < 2; mt++) {
                uint32_t off = SMEM_SWIZZLE_128B((aRow + mt * 16) * 128 + kbA);
                ldsm4(aH[mt], sA_hi + off);
                ldsm4(aL[mt], sA_lo + off);
            }
            uint32_t bH[2][4], bL[2][4];
            const int kbB = ks * 32 + bKoff;
#pragma unroll
            for (int nt = 0; nt < 2; nt++) {
                uint32_t off = SMEM_SWIZZLE_128B((bRow + nt * 16) * 128 + kbB);
                ldsm4(bH[nt], sB_hi + off);
                ldsm4(bL[nt], sB_lo + off);
            }
            // term-major issue order
#pragma unroll
            for (int mt = 0; mt < 2; mt++)
#pragma unroll
                for (int nt = 0; nt < 2; nt++) {
                    mma_bf16(c[mt][nt * 2],     aH[mt], &bH[nt][0]);
                    mma_bf16(c[mt][nt * 2 + 1], aH[mt], &bH[nt][2]);
                }
#pragma unroll
            for (int mt = 0; mt < 2; mt++)
#pragma unroll
                for (int nt = 0; nt < 2; nt++) {
                    mma_bf16(c[mt][nt * 2],     aH[mt], &bL[nt][0]);
                    mma_bf16(c[mt][nt * 2 + 1], aH[mt], &bL[nt][2]);
                }
#pragma unroll
            for (int mt = 0; mt < 2; mt++)
#pragma unroll
                for (int nt = 0; nt < 2; nt++) {
                    mma_bf16(c[mt][nt * 2],     aL[mt], &bH[nt][0]);
                    mma_bf16(c[mt][nt * 2 + 1], aL[mt], &bH[nt][2]);
                }
        }
        // no trailing __syncthreads: next iteration's barrier orders reuse
    }

    const int qr = lane >> 2;
    const int qc = (lane & 3) * 2;
#pragma unroll
    for (int mt = 0; mt < 2; mt++) {
        const int row = rowBase + wm * 32 + mt * 16 + qr;
#pragma unroll
        for (int nt = 0; nt < 4; nt++) {
            const int col = colBase + wn * 32 + nt * 8 + qc;
            float b0 = 0.0f, b1 = 0.0f;
            if (bias) { b0 = bias[col]; b1 = bias[col + 1]; }
            float v00 = c[mt][nt][0] + b0, v01 = c[mt][nt][1] + b1;
            float v10 = c[mt][nt][2] + b0, v11 = c[mt][nt][3] + b1;
            if (outHi) {
                __nv_bfloat16 h00 = __float2bfloat16(v00), h01 = __float2bfloat16(v01);
                __nv_bfloat16 h10 = __float2bfloat16(v10), h11 = __float2bfloat16(v11);
                __nv_bfloat16 l00 = __float2bfloat16(v00 - __bfloat162float(h00));
                __nv_bfloat16 l01 = __float2bfloat16(v01 - __bfloat162float(h01));
                __nv_bfloat16 l10 = __float2bfloat16(v10 - __bfloat162float(h10));
                __nv_bfloat16 l11 = __float2bfloat16(v11 - __bfloat162float(h11));
                *(__nv_bfloat162*)&outHi[(size_t)row * N + col]       = __halves2bfloat162(h00, h01);
                *(__nv_bfloat162*)&outHi[(size_t)(row + 8) * N + col] = __halves2bfloat162(h10, h11);
                *(__nv_bfloat162*)&outLo[(size_t)row * N + col]       = __halves2bfloat162(l00, l01);
                *(__nv_bfloat162*)&outLo[(size_t)(row + 8) * N + col] = __halves2bfloat162(l10, l11);
            } else {
                *(float2*)&C[(size_t)row * N + col]       = make_float2(v00, v01);
                *(float2*)&C[(size_t)(row + 8) * N + col] = make_float2(v10, v11);
            }
        }
    }
}

// ---------------------------------------------------------------------------
// FA2-style HMMA flash attention: 128q x 64k tiles, 8 warps x 16 rows each,
// register-resident softmax (quad shuffles), P fed to PV straight from regs,
// double-buffered K/V/mask via cp.async. Split-bf16 (3-term) both MMAs.
// ---------------------------------------------------------------------------
// smem byte offsets (from 1KB-aligned base)
#define A_OQH   0                     // Q hi: 128 x 256B = 32KB
#define A_OQL   32768                 // Q lo: 32KB
#define A_OKV   65536                 // 2 stages x 64KB: KH|KL|VH|VL (16KB each)
#define A_OMSK  196608                // 2 stages x 8KB mask
#define ATTN_SMEM_BYTES (212992 + 1024)

__global__ void __launch_bounds__(256, 1)
attn_mma_kernel(const __nv_bfloat16* __restrict__ Mhi,
                const __nv_bfloat16* __restrict__ Mlo,
                const unsigned char* __restrict__ mask,
                __nv_bfloat16* __restrict__ ctxHi,
                __nv_bfloat16* __restrict__ ctxLo)
{
    extern __shared__ char smraw[];
    uint32_t sraw = smem_u32(smraw);
    const uint32_t sb = (sraw + 1023u) & ~1023u;

    const int tid  = threadIdx.x;
    const int lane = tid & 31;
    const int warp = tid >> 5;            // 0..7, owns rows warp*16..+15
    const int gr   = lane >> 2;           // 0..7 row-in-group
    const int tg   = lane & 3;            // quad col group
    const int qc   = tg * 2;

    const int qt = (gridDim.x - 1) - blockIdx.x;   // heavy blocks first
    const int q0 = qt * 128;
    const int h  = blockIdx.y;
    const int b  = blockIdx.z;
    const size_t headOff = (size_t)b * QKV_N + h * (3 * DHEAD);
    const unsigned char* mb = mask + (size_t)b * S_LEN * S_LEN;

    // ---- issue Q hi/lo loads (own commit group) ----
#pragma unroll
    for (int i = 0; i < 16; i++) {
        int s = tid + i * 256;          // 0..4095
        int half = s >> 11;
        int s2 = s & 2047;
        int r = s2 >> 4, c16 = s2 & 15;
        const __nv_bfloat16* src = (half ? Mlo : Mhi) +
            (size_t)(q0 + r) * MROW + headOff + c16 * 8;
        uint32_t d = sb + (half ? A_OQL : A_OQH) + swz256(r, c16 * 16);
        CP_ASYNC16(d, src);
    }
    CP_COMMIT();

    auto issue_kv = [&](int stage, int t) {
        const int k0 = t * 64;
        const uint32_t kvb = sb + A_OKV + stage * 65536;
#pragma unroll
        for (int i = 0; i < 16; i++) {
            int s = tid + i * 256;      // 0..4095
            int ts = s >> 10;           // 0:KH 1:KL 2:VH 3:VL
            int s2 = s & 1023;
            int r = s2 >> 4, c16 = s2 & 15;
            const __nv_bfloat16* src = ((ts & 1) ? Mlo : Mhi) +
                (size_t)(k0 + r) * MROW + headOff + ((ts < 2) ? DHEAD : 2 * DHEAD) + c16 * 8;
            CP_ASYNC16(kvb + ts * 16384 + swz256(r, c16 * 16), src);
        }
        const uint32_t mkb = sb + A_OMSK + stage * 8192;
#pragma unroll
        for (int i = 0; i < 2; i++) {
            int cid = tid + i * 256;    // 0..511
            int r = cid >> 2, c16 = cid & 3;
            const void* src = mb + (size_t)(q0 + r) * S_LEN + t * 64 + c16 * 16;
            CP_ASYNC16(mkb + r * 64 + c16 * 16, src);
        }
    };

    issue_kv(0, 0);
    CP_COMMIT();

    float accO[16][4];
#pragma unroll
    for (int nt = 0; nt < 16; nt++)
#pragma unroll
        for (int j = 0; j < 4; j++) accO[nt][j] = 0.0f;

    float m0 = -1e30f, m1 = -1e30f, l0 = 0.0f, l1 = 0.0f;
    const float scale = 0.0883883476483184405f;   // 1/sqrt(128)
    const int lr = lane & 7, mi = lane >> 3;

    const int ntiles = 2 * qt + 2;
    for (int t = 0; t < ntiles; t++) {
        const int st = t & 1;
        if (t + 1 < ntiles) issue_kv((t + 1) & 1, t + 1);
        CP_COMMIT();
        CP_WAIT1();
        __syncthreads();

        const uint32_t sKH = sb + A_OKV + st * 65536;
        const uint32_t sKL = sKH + 16384;
        const uint32_t sVH = sKH + 32768;
        const uint32_t sVL = sKH + 49152;
        const uint32_t sMsk = sb + A_OMSK + st * 8192;
        const int k0 = t * 64;

        // ================= QK^T =================
        float s_[8][4];
#pragma unroll
        for (int nt = 0; nt < 8; nt++)
#pragma unroll
            for (int j = 0; j < 4; j++) s_[nt][j] = 0.0f;

#pragma unroll
        for (int ks = 0; ks < 8; ks++) {
            uint32_t aH[4], aL[4];
            {
                uint32_t off = swz256(warp * 16 + (lane & 15),
                                      ks * 32 + ((lane >> 4) << 4));
                ldsm4(aH, sb + A_OQH + off);
                ldsm4(aL, sb + A_OQL + off);
            }
            uint32_t bH[4][4], bL[4][4];
            const uint32_t bByte = ks * 32 + (((lane >> 3) & 1) << 4);
#pragma unroll
            for (int p = 0; p < 4; p++) {
                uint32_t off = swz256(p * 16 + (lane & 7) + ((lane >> 4) << 3), bByte);
                ldsm4(bH[p], sKH + off);
                ldsm4(bL[p], sKL + off);
            }
            // term-major: 8-issue same-acc gap
#pragma unroll
            for (int p = 0; p < 4; p++) {
                mma_bf16(s_[p * 2],     aH, &bH[p][0]);
                mma_bf16(s_[p * 2 + 1], aH, &bH[p][2]);
            }
#pragma unroll
            for (int p = 0; p < 4; p++) {
                mma_bf16(s_[p * 2],     aH, &bL[p][0]);
                mma_bf16(s_[p * 2 + 1], aH, &bL[p][2]);
            }
#pragma unroll
            for (int p = 0; p < 4; p++) {
                mma_bf16(s_[p * 2],     aL, &bH[p][0]);
                mma_bf16(s_[p * 2 + 1], aL, &bH[p][2]);
            }
        }

        // ---- scale + padding mask + (causal on diagonal tiles) ----
        const int r0 = q0 + warp * 16 + gr;
        const int r1 = r0 + 8;
        const bool diag = (t >= 2 * qt);
#pragma unroll
        for (int nt = 0; nt < 8; nt++) {
            const int c = nt * 8 + qc;
            unsigned short mpair0, mpair1;
            asm volatile("ld.shared.u16 %0, [%1];" : "=h"(mpair0)
                         : "r"(sMsk + (warp * 16 + gr) * 64 + c));
            asm volatile("ld.shared.u16 %0, [%1];" : "=h"(mpair1)
                         : "r"(sMsk + (warp * 16 + gr + 8) * 64 + c));
            float v0 = s_[nt][0] * scale, v1 = s_[nt][1] * scale;
            float v2 = s_[nt][2] * scale, v3 = s_[nt][3] * scale;
            if (mpair0 & 0x00FF) v0 = -10000.0f;
            if (mpair0 & 0xFF00) v1 = -10000.0f;
            if (mpair1 & 0x00FF) v2 = -10000.0f;
            if (mpair1 & 0xFF00) v3 = -10000.0f;
            if (diag) {
                if (k0 + c     > r0) v0 = -10000.0f;
                if (k0 + c + 1 > r0) v1 = -10000.0f;
                if (k0 + c     > r1) v2 = -10000.0f;
                if (k0 + c + 1 > r1) v3 = -10000.0f;
            }
            s_[nt][0] = v0; s_[nt][1] = v1; s_[nt][2] = v2; s_[nt][3] = v3;
        }

        // ---- row max (registers + quad shuffles) ----
        float mx0 = -1e30f, mx1 = -1e30f;
#pragma unroll
        for (int nt = 0; nt < 8; nt++) {
            mx0 = fmaxf(mx0, fmaxf(s_[nt][0], s_[nt][1]));
            mx1 = fmaxf(mx1, fmaxf(s_[nt][2], s_[nt][3]));
        }
        mx0 = fmaxf(mx0, __shfl_xor_sync(0xffffffffu, mx0, 1));
        mx0 = fmaxf(mx0, __shfl_xor_sync(0xffffffffu, mx0, 2));
        mx1 = fmaxf(mx1, __shfl_xor_sync(0xffffffffu, mx1, 1));
        mx1 = fmaxf(mx1, __shfl_xor_sync(0xffffffffu, mx1, 2));

        const float mn0 = fmaxf(m0, mx0);
        const float mn1 = fmaxf(m1, mx1);
        const float al0 = __expf(m0 - mn0);
        const float al1 = __expf(m1 - mn1);
        m0 = mn0; m1 = mn1;

        // ---- exp + row sums ----
        float sm0 = 0.0f, sm1 = 0.0f;
#pragma unroll
        for (int nt = 0; nt < 8; nt++) {
            float p0 = __expf(s_[nt][0] - mn0);
            float p1 = __expf(s_[nt][1] - mn0);
            float p2 = __expf(s_[nt][2] - mn1);
            float p3 = __expf(s_[nt][3] - mn1);
            sm0 += p0 + p1; sm1 += p2 + p3;
            s_[nt][0] = p0; s_[nt][1] = p1; s_[nt][2] = p2; s_[nt][3] = p3;
        }
        sm0 += __shfl_xor_sync(0xffffffffu, sm0, 1);
        sm0 += __shfl_xor_sync(0xffffffffu, sm0, 2);
        sm1 += __shfl_xor_sync(0xffffffffu, sm1, 1);
        sm1 += __shfl_xor_sync(0xffffffffu, sm1, 2);
        l0 = l0 * al0 + sm0;
        l1 = l1 * al1 + sm1;

        // ---- rescale accO ----
#pragma unroll
        for (int nt = 0; nt < 16; nt++) {
            accO[nt][0] *= al0; accO[nt][1] *= al0;
            accO[nt][2] *= al1; accO[nt][3] *= al1;
        }

        // ================= P @ V (P from registers) =================
#pragma unroll
        for (int ks = 0; ks < 4; ks++) {
            // A-frags for keys ks*16..+15 from P register split
            uint32_t pH[4], pL[4];
            {
                const float* e0 = s_[2 * ks];
                const float* e1 = s_[2 * ks + 1];
                __nv_bfloat16 h00 = __float2bfloat16(e0[0]), h01 = __float2bfloat16(e0[1]);
                __nv_bfloat16 h02 = __float2bfloat16(e0[2]), h03 = __float2bfloat16(e0[3]);
                __nv_bfloat16 h10 = __float2bfloat16(e1[0]), h11 = __float2bfloat16(e1[1]);
                __nv_bfloat16 h12 = __float2bfloat16(e1[2]), h13 = __float2bfloat16(e1[3]);
                __nv_bfloat162 a0 = __halves2bfloat162(h00, h01);
                __nv_bfloat162 a1 = __halves2bfloat162(h02, h03);
                __nv_bfloat162 a2 = __halves2bfloat162(h10, h11);
                __nv_bfloat162 a3 = __halves2bfloat162(h12, h13);
                pH[0] = *(uint32_t*)&a0; pH[1] = *(uint32_t*)&a1;
                pH[2] = *(uint32_t*)&a2; pH[3] = *(uint32_t*)&a3;
                __nv_bfloat16 g00 = __float2bfloat16(e0[0] - __bfloat162float(h00));
                __nv_bfloat16 g01 = __float2bfloat16(e0[1] - __bfloat162float(h01));
                __nv_bfloat16 g02 = __float2bfloat16(e0[2] - __bfloat162float(h02));
                __nv_bfloat16 g03 = __float2bfloat16(e0[3] - __bfloat162float(h03));
                __nv_bfloat16 g10 = __float2bfloat16(e1[0] - __bfloat162float(h10));
                __nv_bfloat16 g11 = __float2bfloat16(e1[1] - __bfloat162float(h11));
                __nv_bfloat16 g12 = __float2bfloat16(e1[2] - __bfloat162float(h12));
                __nv_bfloat16 g13 = __float2bfloat16(e1[3] - __bfloat162float(h13));
                __nv_bfloat162 c0 = __halves2bfloat162(g00, g01);
                __nv_bfloat162 c1 = __halves2bfloat162(g02, g03);
                __nv_bfloat162 c2 = __halves2bfloat162(g10, g11);
                __nv_bfloat162 c3 = __halves2bfloat162(g12, g13);
                pL[0] = *(uint32_t*)&c0; pL[1] = *(uint32_t*)&c1;
                pL[2] = *(uint32_t*)&c2; pL[3] = *(uint32_t*)&c3;
            }
            const uint32_t vrow = ks * 16 + ((mi & 1) << 3) + lr;
            // two halves of 4 np each to bound live registers
#pragma unroll
            for (int hh = 0; hh < 2; hh++) {
                uint32_t vh[4][4], vl[4][4];
#pragma unroll
                for (int np = 0; np < 4; np++) {
                    uint32_t vbyte = (hh * 4 + np) * 32 + ((mi >> 1) << 4);
                    uint32_t off = swz256(vrow, vbyte);
                    ldsm4t(vh[np], sVH + off);
                    ldsm4t(vl[np], sVL + off);
                }
                float (*aO)[4] = &accO[hh * 8];
#pragma unroll
                for (int np = 0; np < 4; np++) {
                    mma_bf16(aO[np * 2],     pH, &vh[np][0]);
                    mma_bf16(aO[np * 2 + 1], pH, &vh[np][2]);
                }
#pragma unroll
                for (int np = 0; np < 4; np++) {
                    mma_bf16(aO[np * 2],     pH, &vl[np][0]);
                    mma_bf16(aO[np * 2 + 1], pH, &vl[np][2]);
                }
#pragma unroll
                for (int np = 0; np < 4; np++) {
                    mma_bf16(aO[np * 2],     pL, &vh[np][0]);
                    mma_bf16(aO[np * 2 + 1], pL, &vh[np][2]);
                }
            }
        }
        __syncthreads();   // all warps done with this stage's K/V/mask
    }

    // ---- epilogue: O/l -> split bf16 ctx ----
    const float inv0 = 1.0f / l0;
    const float inv1 = 1.0f / l1;
    const int row0 = q0 + warp * 16 + gr;
    const size_t base0 = ((size_t)row0 * BATCH + b) * HID + h * DHEAD;
    const size_t base1 = ((size_t)(row0 + 8) * BATCH + b) * HID + h * DHEAD;
#pragma unroll
    for (int nt = 0; nt < 16; nt++) {
        const int col = nt * 8 + qc;
        float v00 = accO[nt][0] * inv0, v01 = accO[nt][1] * inv0;
        float v10 = accO[nt][2] * inv1, v11 = accO[nt][3] * inv1;
        __nv_bfloat16 h00 = __float2bfloat16(v00), h01 = __float2bfloat16(v01);
        __nv_bfloat16 h10 = __float2bfloat16(v10), h11 = __float2bfloat16(v11);
        __nv_bfloat16 l00 = __float2bfloat16(v00 - __bfloat162float(h00));
        __nv_bfloat16 l01 = __float2bfloat16(v01 - __bfloat162float(h01));
        __nv_bfloat16 l10 = __float2bfloat16(v10 - __bfloat162float(h10));
        __nv_bfloat16 l11 = __float2bfloat16(v11 - __bfloat162float(h11));
        *(__nv_bfloat162*)&ctxHi[base0 + col] = __halves2bfloat162(h00, h01);
        *(__nv_bfloat162*)&ctxHi[base1 + col] = __halves2bfloat162(h10, h11);
        *(__nv_bfloat162*)&ctxLo[base0 + col] = __halves2bfloat162(l00, l01);
        *(__nv_bfloat162*)&ctxLo[base1 + col] = __halves2bfloat162(l10, l11);
    }
}

__global__ void bias_tail_kernel(const float* __restrict__ proj_bias,
                                 float* __restrict__ out_tail)
{
    int i = blockIdx.x * blockDim.x + threadIdx.x;
    if (i < HID) out_tail[i] = proj_bias[i];
}

// ---------------------------------------------------------------------------
extern "C" void kernel_launch(void* const* d_in, const int* in_sizes, int n_in,
                              void* d_out, int out_size)
{
    const float* hidden      = (const float*)d_in[0];
    const unsigned char* msk = (const unsigned char*)d_in[1];
    const float* qkv_w       = (const float*)d_in[2];
    const float* qkv_b       = (const float*)d_in[3];
    const float* proj_w      = (const float*)d_in[4];
    const float* proj_b      = (const float*)d_in[5];
    float* out               = (float*)d_out;

    __nv_bfloat16 *mHi, *mLo, *aHi, *aLo, *wqHi, *wqLo, *wpHi, *wpLo;
    cudaGetSymbolAddress((void**)&mHi, g_Mhi);
    cudaGetSymbolAddress((void**)&mLo, g_Mlo);
    cudaGetSymbolAddress((void**)&aHi, g_Ahi);
    cudaGetSymbolAddress((void**)&aLo, g_Alo);
    cudaGetSymbolAddress((void**)&wqHi, g_WqT_hi);
    cudaGetSymbolAddress((void**)&wqLo, g_WqT_lo);
    cudaGetSymbolAddress((void**)&wpHi, g_WpT_hi);
    cudaGetSymbolAddress((void**)&wpLo, g_WpT_lo);

    cudaFuncSetAttribute(attn_mma_kernel,
                         cudaFuncAttributeMaxDynamicSharedMemorySize, ATTN_SMEM_BYTES);
    cudaFuncSetAttribute(gemm_mma_kernel,
                         cudaFuncAttributeMaxDynamicSharedMemorySize, G_SMEM_BYTES);

    // 0) Weight transpose + split, activation split
    {
        dim3 blk(32, 8);
        transpose_split_kernel<<<dim3(QKV_N / 32, HID / 32), blk>>>(qkv_w, wqHi, wqLo, HID, QKV_N);
        transpose_split_kernel<<<dim3(HID / 32, HID / 32), blk>>>(proj_w, wpHi, wpLo, HID, HID);
        int n4 = ROWS * HID / 4;
        split_kernel<<<(n4 + 255) / 256, 256>>>(hidden, aHi, aLo, n4);
    }
    // 1) QKV GEMM -> split-bf16 mixed
    {
        dim3 grid(QKV_N / 128, ROWS / 128);
        gemm_mma_kernel<<<grid, 512, G_SMEM_BYTES>>>(ROWS, QKV_N, HID,
                                                     aHi, aLo, wqHi, wqLo, qkv_b,
                                                     nullptr, mHi, mLo);
    }
    // 2) FA2 HMMA attention -> split-bf16 ctx (into proj input buffers)
    {
        dim3 grid(S_LEN / 128, NHEAD, BATCH);
        attn_mma_kernel<<<grid, 256, ATTN_SMEM_BYTES>>>(mHi, mLo, msk, aHi, aLo);
    }
    // 3) Projection: out = ctx @ proj_w (fp32 out)
    {
        dim3 grid(HID / 128, ROWS / 128);
        gemm_mma_kernel<<<grid, 512, G_SMEM_BYTES>>>(ROWS, HID, HID,
                                                     aHi, aLo, wpHi, wpLo,
                                                     (const float*)nullptr, out,
                                                     nullptr, nullptr);
    }
    // 4) Tail: proj_bias after main output
    bias_tail_kernel<<<(HID + 255) / 256, 256>>>(proj_b, out + (size_t)ROWS * HID);
}